// round 12
// baseline (speedup 1.0000x reference)
#include <cuda_runtime.h>
#include <cuda_fp16.h>
#include <cstdint>
#include <math.h>

#define CIN   1024
#define FFD   512
#define OUTD  128
#define NTOT  4096
#define KCONV 27648
#define PCONV 1568
#define BT    24
#define NS    1024
#define SMEMB 98304   // 3 stages x 32KB

// ---------- fp32 scratch ----------
__device__ float g_x[(size_t)NTOT * CIN];
__device__ float g_y[(size_t)NTOT * CIN];
__device__ float g_v[(size_t)NTOT * FFD];
__device__ float g_conv[(size_t)PCONV * FFD];
__device__ float g_gp[4 * FFD];
__device__ float g_fb[(size_t)(BT * 64) * CIN];
__device__ float g_w1t[4 * FFD * CIN];
__device__ float g_w2t[4 * FFD * FFD];
__device__ float g_s1[(size_t)(BT * 256) * FFD];
__device__ float g_s2[(size_t)(BT * 1024) * FFD];
__device__ float g_pe[(size_t)NS * FFD];
__device__ float g_attn[BT * NS];
__device__ float g_sga[BT * FFD];
__device__ float g_bns[2048];
// ---------- packed fp16 operands: [chunk of 64 K][row][128B = 64 fp16] ----------
__device__ uint4 pk_x[16 * NTOT * 8];
__device__ uint4 pk_v[8 * NTOT * 8];
__device__ uint4 pk_fb[16 * (BT * 64) * 8];
__device__ uint4 pk_s1[8 * (BT * 1024) * 8];
__device__ uint4 pk_wc[432 * FFD * 8];
__device__ uint4 pk_vw[2][16 * FFD * 8];
__device__ uint4 pk_ow[2][8 * CIN * 8];
__device__ uint4 pk_w1[4 * 16 * FFD * 8];
__device__ uint4 pk_w2[4 * 8 * FFD * 8];

// ---------- helpers ----------
__device__ __forceinline__ uint32_t smem_u32(const void* p) {
    uint32_t a;
    asm("{ .reg .u64 t; cvta.to.shared.u64 t, %1; cvt.u32.u64 %0, t; }" : "=r"(a) : "l"(p));
    return a;
}
#define LDSM4(r0, r1, r2, r3, addr) \
    asm volatile("ldmatrix.sync.aligned.m8n8.x4.shared.b16 {%0,%1,%2,%3}, [%4];" \
        : "=r"(r0), "=r"(r1), "=r"(r2), "=r"(r3) : "r"(addr))
#define MMA(c, a, b0, b1) \
    asm volatile("mma.sync.aligned.m16n8k16.row.col.f32.f16.f16.f32 " \
        "{%0,%1,%2,%3},{%4,%5,%6,%7},{%8,%9},{%0,%1,%2,%3};" \
        : "+f"((c)[0]), "+f"((c)[1]), "+f"((c)[2]), "+f"((c)[3]) \
        : "r"((a)[0]), "r"((a)[1]), "r"((a)[2]), "r"((a)[3]), "r"(b0), "r"(b1))
#define CP16(dst, src) \
    asm volatile("cp.async.cg.shared.global [%0], [%1], 16;" :: "r"(dst), "l"(src))
#define CPCOMMIT() asm volatile("cp.async.commit_group;" ::: "memory")
#define CPWAIT(n)  asm volatile("cp.async.wait_group %0;" :: "n"(n) : "memory")

__device__ __forceinline__ uint32_t pk2(float hi, float lo) {   // {hi:lo} fp16x2
    uint32_t r;
    asm("cvt.rn.f16x2.f32 %0, %1, %2;" : "=r"(r) : "f"(hi), "f"(lo));
    return r;
}
__device__ __forceinline__ uint4 pack8(float4 a, float4 b) {
    uint4 h;
    h.x = pk2(a.y, a.x); h.y = pk2(a.w, a.z);
    h.z = pk2(b.y, b.x); h.w = pk2(b.w, b.z);
    return h;
}
__device__ __forceinline__ uint32_t swz(uint32_t o) { return o ^ ((o >> 3) & 0x70u); }

// fp32 [M][K] -> packed fp16 [K/64][M][128B]
__global__ void pack_act(const float* __restrict__ src, uint4* __restrict__ dst, int M, int K) {
    int idx = blockIdx.x * 256 + threadIdx.x;
    int kg = K >> 3;
    int row = idx / kg, u = idx - row * kg;
    int chunk = u >> 3, g = u & 7;
    const float* s = src + (size_t)row * K + u * 8;
    float4 a = *(const float4*)s, b = *(const float4*)(s + 4);
    dst[((size_t)chunk * M + row) * 8 + g] = pack8(a, b);
}
// conv weights (FF, CIN, 27) -> packed fp16 [chunk = rk*16 + c/64][512][128B]
__global__ void pack_wconv(const float* __restrict__ w) {   // grid (512, 4), 256 thr
    __shared__ float st[27][260];
    int f = blockIdx.x, c0 = blockIdx.y * 256;
    const float* src = w + (size_t)f * KCONV + (size_t)c0 * 27;
    for (int i = threadIdx.x; i < 27 * 256; i += 256) {
        int c = i / 27, r = i - c * 27;
        st[r][c] = src[i];
    }
    __syncthreads();
    for (int u = threadIdx.x; u < 27 * 32; u += 256) {
        int r = u >> 5, grp = u & 31;
        const float* p = &st[r][grp * 8];
        float4 a = make_float4(p[0], p[1], p[2], p[3]);
        float4 b = make_float4(p[4], p[5], p[6], p[7]);
        int chunk = r * 16 + (c0 >> 6) + (grp >> 3);
        pk_wc[((size_t)chunk * FFD + f) * 8 + (grp & 7)] = pack8(a, b);
    }
}

// ========== cp.async 3-stage warp-MMA fp16 GEMM, tile 128M x 128N, warp 64x32 ==========
// MODE 0 plain fp32 | 1 xin+relu(v+bias) | 3 up1 scatter relu | 4 up2 scatter | 5 conv atomicAdd
template <int MODE>
__global__ void __launch_bounds__(256, 2) tc_gemm(
    const uint4* __restrict__ Apk, const uint4* __restrict__ Bpk, float* __restrict__ C,
    int Mtot, int Ma, int Nbr, int Sloc, int ldc,
    const float* __restrict__ bias, const float* __restrict__ xin)
{
    extern __shared__ char dsm[];
    const uint32_t smb = smem_u32(dsm);
    const int tid = threadIdx.x, wid = tid >> 5, lane = tid & 31;
    const int wm = wid >> 2, wn = wid & 3;       // 2m x 4n warps, 64x32 each
    const int row0 = blockIdx.x * 128;
    const int colW = blockIdx.y * 128;
    const int z = blockIdx.z;
    const int g0 = (tid & 1) * 4;
    const int arow = tid >> 1;                   // 0..127
    const int kchunk0 = (MODE == 5) ? z * Sloc : 0;
    if (MODE == 3 || MODE == 4) Bpk += (size_t)z * Sloc * Nbr * 8;

    int nbrow;
    {
        int p = row0 + arow;
        if (p >= Mtot) p = Mtot - 1;
        if (MODE == 5) {
            int b = p / 392, q = p % 392;
            int t = q / 196, rem = q % 196, h = rem / 14, w = rem % 14;
            nbrow = (b * 4 + t) * 256 + h * 16 + w;
        } else {
            nbrow = (p >= Ma) ? Ma - 1 : p;
        }
    }
    const uint32_t rbase = (uint32_t)(arow * 128 + g0 * 16);

    auto issue = [&](int s, int buf) {
        int sg = kchunk0 + s;
        uint32_t sb = smb + (uint32_t)buf * 32768u;
        const uint4* asrc;
        if (MODE == 5) {
            int rk = sg >> 4, cc = sg & 15;
            int dt = rk / 9, dh = (rk / 3) % 3, dw = rk - (rk / 3) * 3;
            asrc = Apk + ((size_t)cc * Ma + nbrow + dt * 256 + dh * 16 + dw) * 8 + g0;
        } else {
            asrc = Apk + ((size_t)sg * Ma + nbrow) * 8 + g0;
        }
#pragma unroll
        for (int g = 0; g < 4; g++) {
            uint32_t off = swz(rbase + g * 16);
            CP16(sb + off, asrc + g);
        }
        const uint4* bsrc = Bpk + ((size_t)sg * Nbr + colW + arow) * 8 + g0;
#pragma unroll
        for (int g = 0; g < 4; g++) {
            uint32_t off = swz(rbase + g * 16);
            CP16(sb + 16384u + off, bsrc + g);
        }
        CPCOMMIT();
    };

    float acc[4][4][4];
#pragma unroll
    for (int i = 0; i < 4; i++)
#pragma unroll
        for (int j = 0; j < 4; j++)
#pragma unroll
            for (int e = 0; e < 4; e++) acc[i][j][e] = 0.f;

    issue(0, 0);
    issue(1, 1);

    const int q = lane >> 3, rl = lane & 7;
    for (int s = 0; s < Sloc; s++) {
        if (s + 1 < Sloc) { CPWAIT(1); } else { CPWAIT(0); }
        __syncthreads();
        if (s + 2 < Sloc) issue(s + 2, (s + 2) % 3);
        const uint32_t aB = smb + (uint32_t)(s % 3) * 32768u;
        const uint32_t bB = aB + 16384u;
#pragma unroll
        for (int ks = 0; ks < 4; ks++) {
            uint32_t ah[4][4];
            uint32_t ao = swz((uint32_t)((wm * 64 + (q & 1) * 8 + rl) * 128 + ks * 32 + (q >> 1) * 16));
#pragma unroll
            for (int mt = 0; mt < 4; mt++)
                LDSM4(ah[mt][0], ah[mt][1], ah[mt][2], ah[mt][3], aB + ao + mt * 2048);
            uint32_t bo = swz((uint32_t)((wn * 32 + (q >> 1) * 8 + rl) * 128 + ks * 32 + (q & 1) * 16));
#pragma unroll
            for (int pt = 0; pt < 2; pt++) {
                uint32_t bh[4];
                LDSM4(bh[0], bh[1], bh[2], bh[3], bB + bo + pt * 2048);
#pragma unroll
                for (int mt = 0; mt < 4; mt++) {
                    MMA(acc[mt][2 * pt],     ah[mt], bh[0], bh[1]);
                    MMA(acc[mt][2 * pt + 1], ah[mt], bh[2], bh[3]);
                }
            }
        }
    }

    // epilogue (coalesced float2 per lane-quad)
#pragma unroll
    for (int mt = 0; mt < 4; mt++) {
#pragma unroll
        for (int nt = 0; nt < 4; nt++) {
            int f = colW + wn * 32 + nt * 8 + 2 * (lane & 3);
            float b0 = 0.f, b1 = 0.f;
            if (MODE == 1 || MODE == 3 || MODE == 4) { b0 = bias[f]; b1 = bias[f + 1]; }
#pragma unroll
            for (int hh = 0; hh < 2; hh++) {
                int pos = row0 + wm * 64 + mt * 16 + (lane >> 2) + hh * 8;
                if (pos >= Mtot) continue;
                float v0 = acc[mt][nt][hh * 2], v1 = acc[mt][nt][hh * 2 + 1];
                if (MODE == 0) {
                    *reinterpret_cast<float2*>(&C[(size_t)pos * ldc + f]) = make_float2(v0, v1);
                } else if (MODE == 1) {
                    float2 xv = *reinterpret_cast<const float2*>(&xin[(size_t)pos * ldc + f]);
                    *reinterpret_cast<float2*>(&C[(size_t)pos * ldc + f]) =
                        make_float2(xv.x + fmaxf(v0 + b0, 0.f), xv.y + fmaxf(v1 + b1, 0.f));
                } else if (MODE == 5) {
                    atomicAdd(&C[(size_t)pos * ldc + f], v0);
                    atomicAdd(&C[(size_t)pos * ldc + f + 1], v1);
                } else if (MODE == 3) {
                    int bt = pos >> 6, hw = pos & 63, h = hw >> 3, w = hw & 7;
                    int orow = bt * 256 + (h * 2 + (z >> 1)) * 16 + (w * 2 + (z & 1));
                    *reinterpret_cast<float2*>(&C[(size_t)orow * ldc + f]) =
                        make_float2(fmaxf(v0 + b0, 0.f), fmaxf(v1 + b1, 0.f));
                } else {
                    int bt = pos >> 8, hw = pos & 255, h = hw >> 4, w = hw & 15;
                    int orow = bt * 1024 + (h * 2 + (z >> 1)) * 32 + (w * 2 + (z & 1));
                    *reinterpret_cast<float2*>(&C[(size_t)orow * ldc + f]) =
                        make_float2(v0 + b0, v1 + b1);
                }
            }
        }
    }
}

// ========== misc ==========
__global__ void transpose_ctx(const float* __restrict__ ctx) {
    __shared__ float t[32][33];
    int bt = blockIdx.x, c0 = blockIdx.y * 32, hw0 = blockIdx.z * 32;
    int tx = threadIdx.x, ty = threadIdx.y;
    for (int i = ty; i < 32; i += 8)
        t[i][tx] = ctx[((size_t)bt * 1024 + c0 + i) * 256 + hw0 + tx];
    __syncthreads();
    for (int i = ty; i < 32; i += 8)
        g_x[((size_t)bt * 256 + hw0 + i) * 1024 + c0 + tx] = t[tx][i];
}
__global__ void pack_frame(const float* __restrict__ fr) {
    __shared__ float t[32][33];
    int bt = blockIdx.x, c0 = blockIdx.y * 32, hw0 = blockIdx.z * 32;
    int tx = threadIdx.x, ty = threadIdx.y;
    for (int i = ty; i < 32; i += 8)
        t[i][tx] = fr[((size_t)bt * 1024 + c0 + i) * 64 + hw0 + tx];
    __syncthreads();
    for (int i = ty; i < 32; i += 8)
        g_fb[((size_t)bt * 64 + hw0 + i) * 1024 + c0 + tx] = t[tx][i];
}
__global__ void zero_kernel(float* p, int n) {
    int i = blockIdx.x * blockDim.x + threadIdx.x;
    if (i < n) p[i] = 0.f;
}
__global__ void bn_reduce(const float* __restrict__ y) {
    int c4 = threadIdx.x;
    const float4* y4 = reinterpret_cast<const float4*>(y);
    float4 s = make_float4(0, 0, 0, 0), q = make_float4(0, 0, 0, 0);
    int n0 = blockIdx.x * 32;
    for (int n = n0; n < n0 + 32; n++) {
        float4 v = y4[(size_t)n * 256 + c4];
        s.x += v.x; s.y += v.y; s.z += v.z; s.w += v.w;
        q.x += v.x * v.x; q.y += v.y * v.y; q.z += v.z * v.z; q.w += v.w * v.w;
    }
    atomicAdd(&g_bns[c4 * 4 + 0], s.x); atomicAdd(&g_bns[c4 * 4 + 1], s.y);
    atomicAdd(&g_bns[c4 * 4 + 2], s.z); atomicAdd(&g_bns[c4 * 4 + 3], s.w);
    atomicAdd(&g_bns[1024 + c4 * 4 + 0], q.x); atomicAdd(&g_bns[1024 + c4 * 4 + 1], q.y);
    atomicAdd(&g_bns[1024 + c4 * 4 + 2], q.z); atomicAdd(&g_bns[1024 + c4 * 4 + 3], q.w);
}
// BN apply, writes fp32 x AND packed fp16 qx
__global__ void bn_apply(const float* __restrict__ y, float* __restrict__ xo,
                         uint32_t* __restrict__ qdst,
                         const float* __restrict__ gm, const float* __restrict__ bt) {
    int idx = blockIdx.x * 256 + threadIdx.x;
    int n = idx >> 8, c4 = idx & 255;
    float4 v = reinterpret_cast<const float4*>(y)[idx];
    float4 s = reinterpret_cast<const float4*>(g_bns)[c4];
    float4 q = reinterpret_cast<const float4*>(g_bns + 1024)[c4];
    float4 g = reinterpret_cast<const float4*>(gm)[c4];
    float4 b = reinterpret_cast<const float4*>(bt)[c4];
    const float in = 1.f / NTOT;
    float mx = s.x * in, my = s.y * in, mz = s.z * in, mw = s.w * in;
    float4 r;
    r.x = (v.x - mx) * rsqrtf(q.x * in - mx * mx + 1e-5f) * g.x + b.x;
    r.y = (v.y - my) * rsqrtf(q.y * in - my * my + 1e-5f) * g.y + b.y;
    r.z = (v.z - mz) * rsqrtf(q.z * in - mz * mz + 1e-5f) * g.z + b.z;
    r.w = (v.w - mw) * rsqrtf(q.w * in - mw * mw + 1e-5f) * g.w + b.w;
    reinterpret_cast<float4*>(xo)[idx] = r;
    size_t base = (((size_t)(c4 >> 4) * NTOT + n) * 8 + ((c4 >> 1) & 7)) * 4 + (c4 & 1) * 2;
    qdst[base] = pk2(r.y, r.x);
    qdst[base + 1] = pk2(r.w, r.z);
}
__global__ void goalpre_kernel(const float* __restrict__ tb) {
    int b = blockIdx.x, f = threadIdx.x;
    float bias = tb[f], s = 0.f;
    for (int p = b * 392; p < (b + 1) * 392; p++)
        s += fmaxf(g_conv[(size_t)p * 512 + f] + bias, 0.f);
    g_gp[b * 512 + f] = s * (1.f / 392.f);
}
__global__ void pack_w1(const float* __restrict__ w) {
    int idx = blockIdx.x * 256 + threadIdx.x;
    int c = idx & 1023, o = idx >> 10;
    float4 v = reinterpret_cast<const float4*>(w)[(size_t)c * 512 + o];
    g_w1t[           o * 1024 + c] = v.x;
    g_w1t[ 524288 +  o * 1024 + c] = v.y;
    g_w1t[1048576 +  o * 1024 + c] = v.z;
    g_w1t[1572864 +  o * 1024 + c] = v.w;
}
__global__ void pack_w2(const float* __restrict__ w) {
    int idx = blockIdx.x * 256 + threadIdx.x;
    int c = idx & 511, o = idx >> 9;
    float4 v = reinterpret_cast<const float4*>(w)[(size_t)c * 512 + o];
    g_w2t[          o * 512 + c] = v.x;
    g_w2t[262144 +  o * 512 + c] = v.y;
    g_w2t[524288 +  o * 512 + c] = v.z;
    g_w2t[786432 +  o * 512 + c] = v.w;
}
__global__ void pe_init() {
    int idx = blockIdx.x * 256 + threadIdx.x;
    int n = idx >> 9, c = idx & 511;
    float ang = (float)n * expf(-0.01798894603890390f * (float)(c & ~1));
    g_pe[idx] = (c & 1) ? cosf(ang) : sinf(ang);
}
__global__ void sg_dot() {
    int bt = blockIdx.x, n0 = blockIdx.y * 64;
    int w = threadIdx.x >> 5, lane = threadIdx.x & 31;
    int b = bt / 6;
    const float4* g4 = reinterpret_cast<const float4*>(&g_gp[b * 512]);
#pragma unroll
    for (int j = 0; j < 8; j++) {
        int n = n0 + w * 8 + j;
        const float4* r4 = reinterpret_cast<const float4*>(&g_s2[((size_t)bt * 1024 + n) * 512]);
        float acc = 0.f;
#pragma unroll
        for (int i = 0; i < 4; i++) {
            float4 v = r4[lane + 32 * i], gg = g4[lane + 32 * i];
            acc += v.x * gg.x + v.y * gg.y + v.z * gg.z + v.w * gg.w;
        }
        for (int o = 16; o > 0; o >>= 1) acc += __shfl_down_sync(0xffffffffu, acc, o);
        if (!lane) g_attn[bt * 1024 + n] = acc;
    }
}
__global__ void softmax_norm() {
    int bt = blockIdx.x, tid = threadIdx.x;
    __shared__ float red[256];
    float v[4];
#pragma unroll
    for (int i = 0; i < 4; i++) v[i] = g_attn[bt * 1024 + tid + i * 256];
    float m = fmaxf(fmaxf(v[0], v[1]), fmaxf(v[2], v[3]));
    red[tid] = m; __syncthreads();
    for (int o = 128; o > 0; o >>= 1) { if (tid < o) red[tid] = fmaxf(red[tid], red[tid + o]); __syncthreads(); }
    m = red[0]; __syncthreads();
    float s = 0.f;
#pragma unroll
    for (int i = 0; i < 4; i++) { v[i] = expf(v[i] - m); s += v[i]; }
    red[tid] = s; __syncthreads();
    for (int o = 128; o > 0; o >>= 1) { if (tid < o) red[tid] += red[tid + o]; __syncthreads(); }
    float inv = 1.f / red[0];
#pragma unroll
    for (int i = 0; i < 4; i++) g_attn[bt * 1024 + tid + i * 256] = v[i] * inv;
}
__global__ void sga_kernel() {
    int bt = blockIdx.x, n0 = blockIdx.y * 128, c2 = threadIdx.x;
    float a0 = 0.f, a1 = 0.f;
    for (int n = n0; n < n0 + 128; n++) {
        float at = g_attn[bt * 1024 + n];
        float2 s = *reinterpret_cast<const float2*>(&g_s2[((size_t)bt * 1024 + n) * 512 + c2 * 2]);
        float2 p = *reinterpret_cast<const float2*>(&g_pe[(size_t)n * 512 + c2 * 2]);
        a0 += at * (s.x + p.x); a1 += at * (s.y + p.y);
    }
    atomicAdd(&g_sga[bt * 512 + c2 * 2], a0);
    atomicAdd(&g_sga[bt * 512 + c2 * 2 + 1], a1);
}
__global__ void head_kernel(const float* __restrict__ in,
                            const float* __restrict__ W1, const float* __restrict__ b1,
                            const float* __restrict__ W2, const float* __restrict__ b2,
                            float* __restrict__ out) {
    int r = blockIdx.x, j = threadIdx.x;
    __shared__ float xin[512], t[512];
    xin[j] = in[r * 512 + j];
    __syncthreads();
    float acc = b1[j];
    const float* w = W1 + (size_t)j * 512;
    for (int k = 0; k < 512; k++) acc += xin[k] * w[k];
    t[j] = fmaxf(acc, 0.f);
    __syncthreads();
    if (j < OUTD) {
        float a2 = b2[j];
        const float* w2 = W2 + (size_t)j * 512;
        for (int k = 0; k < 512; k++) a2 += t[k] * w2[k];
        out[r * OUTD + j] = a2;
    }
}

// ---------- launch ----------
extern "C" void kernel_launch(void* const* d_in, const int* in_sizes, int n_in,
                              void* d_out, int out_size) {
    const float* ctx   = (const float*)d_in[0];
    const float* frame = (const float*)d_in[1];
    const float* nl_vw[2]   = { (const float*)d_in[4],  (const float*)d_in[11] };
    const float* nl_ow[2]   = { (const float*)d_in[5],  (const float*)d_in[12] };
    const float* nl_ob[2]   = { (const float*)d_in[6],  (const float*)d_in[13] };
    const float* nl_g[2]    = { (const float*)d_in[7],  (const float*)d_in[14] };
    const float* nl_beta[2] = { (const float*)d_in[8],  (const float*)d_in[15] };
    const float* tp_w  = (const float*)d_in[16];
    const float* tp_b  = (const float*)d_in[17];
    const float* up1_w = (const float*)d_in[18];
    const float* up1_b = (const float*)d_in[19];
    const float* up2_w = (const float*)d_in[20];
    const float* up2_b = (const float*)d_in[21];
    float* out = (float*)d_out;

    float *px, *py, *pv, *pconv, *pw1t, *pw2t, *ps1, *ps2, *pfb, *pgp, *psga, *pbns;
    cudaGetSymbolAddress((void**)&px, g_x);
    cudaGetSymbolAddress((void**)&py, g_y);
    cudaGetSymbolAddress((void**)&pv, g_v);
    cudaGetSymbolAddress((void**)&pconv, g_conv);
    cudaGetSymbolAddress((void**)&pw1t, g_w1t);
    cudaGetSymbolAddress((void**)&pw2t, g_w2t);
    cudaGetSymbolAddress((void**)&ps1, g_s1);
    cudaGetSymbolAddress((void**)&ps2, g_s2);
    cudaGetSymbolAddress((void**)&pfb, g_fb);
    cudaGetSymbolAddress((void**)&pgp, g_gp);
    cudaGetSymbolAddress((void**)&psga, g_sga);
    cudaGetSymbolAddress((void**)&pbns, g_bns);
    uint4 *qx, *qv, *qfb, *qs1, *qwc, *qvw0, *qvw1, *qow0, *qow1, *qw1, *qw2;
    cudaGetSymbolAddress((void**)&qx, pk_x);
    cudaGetSymbolAddress((void**)&qv, pk_v);
    cudaGetSymbolAddress((void**)&qfb, pk_fb);
    cudaGetSymbolAddress((void**)&qs1, pk_s1);
    cudaGetSymbolAddress((void**)&qwc, pk_wc);
    cudaGetSymbolAddress((void**)&qvw0, pk_vw); qvw1 = qvw0 + 16 * FFD * 8;
    cudaGetSymbolAddress((void**)&qow0, pk_ow); qow1 = qow0 + 8 * CIN * 8;
    cudaGetSymbolAddress((void**)&qw1, pk_w1);
    cudaGetSymbolAddress((void**)&qw2, pk_w2);
    uint4* qvw[2] = { qvw0, qvw1 };
    uint4* qow[2] = { qow0, qow1 };

    cudaFuncSetAttribute(tc_gemm<0>, cudaFuncAttributeMaxDynamicSharedMemorySize, SMEMB);
    cudaFuncSetAttribute(tc_gemm<1>, cudaFuncAttributeMaxDynamicSharedMemorySize, SMEMB);
    cudaFuncSetAttribute(tc_gemm<3>, cudaFuncAttributeMaxDynamicSharedMemorySize, SMEMB);
    cudaFuncSetAttribute(tc_gemm<4>, cudaFuncAttributeMaxDynamicSharedMemorySize, SMEMB);
    cudaFuncSetAttribute(tc_gemm<5>, cudaFuncAttributeMaxDynamicSharedMemorySize, SMEMB);

    // launches 1-3 are the V-GEMM deps, so #4 (profiled) is tc_gemm<0>
    transpose_ctx<<<dim3(16, 32, 8), dim3(32, 8)>>>(ctx);                    // 1
    pack_act<<<(NTOT * CIN / 8) / 256, 256>>>(px, qx, NTOT, 1024);           // 2
    pack_act<<<(512 * 1024 / 8) / 256, 256>>>(nl_vw[0], qvw[0], 512, 1024);  // 3
    tc_gemm<0><<<dim3(32, 4), 256, SMEMB>>>(                                 // 4 (profiled)
        qx, qvw[0], pv, NTOT, NTOT, 512, 16, 512, nullptr, nullptr);

    pack_act<<<(1024 * 512 / 8) / 256, 256>>>(nl_ow[0], qow[0], 1024, 512);
    pack_act<<<(512 * 1024 / 8) / 256, 256>>>(nl_vw[1], qvw[1], 512, 1024);
    pack_act<<<(1024 * 512 / 8) / 256, 256>>>(nl_ow[1], qow[1], 1024, 512);
    pe_init<<<2048, 256>>>();
    pack_frame<<<dim3(24, 32, 2), dim3(32, 8)>>>(frame);
    pack_act<<<(1536 * 1024 / 8) / 256, 256>>>(pfb, qfb, 1536, 1024);
    pack_w1<<<2048, 256>>>(up1_w);
    for (int kl = 0; kl < 4; kl++)
        pack_act<<<(512 * 1024 / 8) / 256, 256>>>(pw1t + (size_t)kl * 524288,
                                                  qw1 + (size_t)kl * 16 * 512 * 8, 512, 1024);
    pack_w2<<<1024, 256>>>(up2_w);
    for (int kl = 0; kl < 4; kl++)
        pack_act<<<(512 * 512 / 8) / 256, 256>>>(pw2t + (size_t)kl * 262144,
                                                 qw2 + (size_t)kl * 8 * 512 * 8, 512, 512);
    pack_wconv<<<dim3(512, 4), 256>>>(tp_w);
    zero_kernel<<<(PCONV * 512 + 255) / 256, 256>>>(pconv, PCONV * 512);

    for (int l = 0; l < 2; l++) {
        if (l == 1)
            tc_gemm<0><<<dim3(32, 4), 256, SMEMB>>>(
                qx, qvw[1], pv, NTOT, NTOT, 512, 16, 512, nullptr, nullptr);
        pack_act<<<(NTOT * 512 / 8) / 256, 256>>>(pv, qv, NTOT, 512);
        tc_gemm<1><<<dim3(32, 8), 256, SMEMB>>>(
            qv, qow[l], py, NTOT, NTOT, 1024, 8, 1024, nl_ob[l], px);
        zero_kernel<<<8, 256>>>(pbns, 2048);
        bn_reduce<<<128, 256>>>(py);
        bn_apply<<<4096, 256>>>(py, px, (uint32_t*)qx, nl_g[l], nl_beta[l]);
    }

    // conv3d: packed A gathered from pk_x, z = 6 K-splits of 72 chunks (432 total)
    tc_gemm<5><<<dim3(13, 4, 6), 256, SMEMB>>>(
        qx, qwc, pconv, PCONV, NTOT, 512, 72, 512, nullptr, nullptr);
    goalpre_kernel<<<4, 512>>>(tp_b);

    tc_gemm<3><<<dim3(12, 4, 4), 256, SMEMB>>>(
        qfb, qw1, ps1, 1536, 1536, 512, 16, 512, up1_b, nullptr);
    pack_act<<<(6144 * 512 / 8) / 256, 256>>>(ps1, qs1, 6144, 512);
    tc_gemm<4><<<dim3(48, 4, 4), 256, SMEMB>>>(
        qs1, qw2, ps2, 6144, 6144, 512, 8, 512, up2_b, nullptr);

    sg_dot<<<dim3(24, 16), 256>>>();
    softmax_norm<<<24, 256>>>();
    zero_kernel<<<48, 256>>>(psga, BT * 512);
    sga_kernel<<<dim3(24, 8), 256>>>();

    head_kernel<<<4, 512>>>(pgp, (const float*)d_in[22], (const float*)d_in[23],
                            (const float*)d_in[24], (const float*)d_in[25], out);
    head_kernel<<<BT, 512>>>(psga, (const float*)d_in[26], (const float*)d_in[27],
                             (const float*)d_in[28], (const float*)d_in[29], out + 4 * OUTD);
}

// round 13
// speedup vs baseline: 1.0605x; 1.0605x over previous
#include <cuda_runtime.h>
#include <cuda_fp16.h>
#include <cstdint>
#include <math.h>

#define CIN   1024
#define FFD   512
#define OUTD  128
#define NTOT  4096
#define KCONV 27648
#define PCONV 1568
#define BT    24
#define NS    1024
#define SM64  73728    // 3 x (8KB A + 16KB B)
#define SM128 98304    // 3 x (16KB A + 16KB B)

// ---------- fp32 scratch ----------
__device__ float g_x[(size_t)NTOT * CIN];
__device__ float g_y[(size_t)NTOT * CIN];
__device__ float g_v[(size_t)NTOT * FFD];
__device__ float g_conv[(size_t)PCONV * FFD];
__device__ float g_gp[4 * FFD];
__device__ float g_fb[(size_t)(BT * 64) * CIN];
__device__ float g_w1t[4 * FFD * CIN];
__device__ float g_w2t[4 * FFD * FFD];
__device__ float g_s1[(size_t)(BT * 256) * FFD];
__device__ float g_s2[(size_t)(BT * 1024) * FFD];
__device__ float g_pe[(size_t)NS * FFD];
__device__ float g_attn[BT * NS];
__device__ float g_sga[BT * FFD];
__device__ float g_bns[2048];
// ---------- packed fp16 operands: [chunk of 64 K][row][128B = 64 fp16] ----------
__device__ uint4 pk_x[16 * NTOT * 8];
__device__ uint4 pk_v[8 * NTOT * 8];
__device__ uint4 pk_fb[16 * (BT * 64) * 8];
__device__ uint4 pk_s1[8 * (BT * 1024) * 8];
__device__ uint4 pk_wc[432 * FFD * 8];
__device__ uint4 pk_vw[2][16 * FFD * 8];
__device__ uint4 pk_ow[2][8 * CIN * 8];
__device__ uint4 pk_w1[4 * 16 * FFD * 8];
__device__ uint4 pk_w2[4 * 8 * FFD * 8];

// ---------- helpers ----------
__device__ __forceinline__ uint32_t smem_u32(const void* p) {
    uint32_t a;
    asm("{ .reg .u64 t; cvta.to.shared.u64 t, %1; cvt.u32.u64 %0, t; }" : "=r"(a) : "l"(p));
    return a;
}
#define LDSM4(r0, r1, r2, r3, addr) \
    asm volatile("ldmatrix.sync.aligned.m8n8.x4.shared.b16 {%0,%1,%2,%3}, [%4];" \
        : "=r"(r0), "=r"(r1), "=r"(r2), "=r"(r3) : "r"(addr))
#define MMA(c, a, b0, b1) \
    asm volatile("mma.sync.aligned.m16n8k16.row.col.f32.f16.f16.f32 " \
        "{%0,%1,%2,%3},{%4,%5,%6,%7},{%8,%9},{%0,%1,%2,%3};" \
        : "+f"((c)[0]), "+f"((c)[1]), "+f"((c)[2]), "+f"((c)[3]) \
        : "r"((a)[0]), "r"((a)[1]), "r"((a)[2]), "r"((a)[3]), "r"(b0), "r"(b1))
#define CP16(dst, src) \
    asm volatile("cp.async.cg.shared.global [%0], [%1], 16;" :: "r"(dst), "l"(src))
#define CPCOMMIT() asm volatile("cp.async.commit_group;" ::: "memory")
#define CPWAIT(n)  asm volatile("cp.async.wait_group %0;" :: "n"(n) : "memory")

__device__ __forceinline__ uint32_t pk2(float hi, float lo) {   // {hi:lo} fp16x2
    uint32_t r;
    asm("cvt.rn.f16x2.f32 %0, %1, %2;" : "=r"(r) : "f"(hi), "f"(lo));
    return r;
}
__device__ __forceinline__ uint4 pack8(float4 a, float4 b) {
    uint4 h;
    h.x = pk2(a.y, a.x); h.y = pk2(a.w, a.z);
    h.z = pk2(b.y, b.x); h.w = pk2(b.w, b.z);
    return h;
}
__device__ __forceinline__ uint32_t swz(uint32_t o) { return o ^ ((o >> 3) & 0x70u); }

// fp32 [M][K] -> packed fp16 [K/64][M][128B]
__global__ void pack_act(const float* __restrict__ src, uint4* __restrict__ dst, int M, int K) {
    int idx = blockIdx.x * 256 + threadIdx.x;
    int kg = K >> 3;
    int row = idx / kg, u = idx - row * kg;
    int chunk = u >> 3, g = u & 7;
    const float* s = src + (size_t)row * K + u * 8;
    float4 a = *(const float4*)s, b = *(const float4*)(s + 4);
    dst[((size_t)chunk * M + row) * 8 + g] = pack8(a, b);
}
// conv weights (FF, CIN, 27) -> packed fp16 [chunk = rk*16 + c/64][512][128B]
__global__ void pack_wconv(const float* __restrict__ w) {   // grid (512, 4), 256 thr
    __shared__ float st[27][260];
    int f = blockIdx.x, c0 = blockIdx.y * 256;
    const float* src = w + (size_t)f * KCONV + (size_t)c0 * 27;
    for (int i = threadIdx.x; i < 27 * 256; i += 256) {
        int c = i / 27, r = i - c * 27;
        st[r][c] = src[i];
    }
    __syncthreads();
    for (int u = threadIdx.x; u < 27 * 32; u += 256) {
        int r = u >> 5, grp = u & 31;
        const float* p = &st[r][grp * 8];
        float4 a = make_float4(p[0], p[1], p[2], p[3]);
        float4 b = make_float4(p[4], p[5], p[6], p[7]);
        int chunk = r * 16 + (c0 >> 6) + (grp >> 3);
        pk_wc[((size_t)chunk * FFD + f) * 8 + (grp & 7)] = pack8(a, b);
    }
}

// ===== cp.async 3-stage warp-MMA fp16 GEMM, tile BM x 128N, warps 2m x 4n =====
// MODE 0 plain fp32 | 1 xin+relu(v+bias) | 3 up1 scatter relu | 4 up2 scatter | 5 conv atomicAdd
template <int MODE, int BM>
__global__ void __launch_bounds__(256, 2) tc_gemm(
    const uint4* __restrict__ Apk, const uint4* __restrict__ Bpk, float* __restrict__ C,
    int Mtot, int Ma, int Nbr, int Sloc, int ldc,
    const float* __restrict__ bias, const float* __restrict__ xin)
{
    constexpr int MT = BM / 32;              // m16 tiles per warp
    constexpr uint32_t ABYTES = BM * 128;
    constexpr uint32_t STRIDE = ABYTES + 16384;
    extern __shared__ char dsm[];
    const uint32_t smb = smem_u32(dsm);
    const int tid = threadIdx.x, wid = tid >> 5, lane = tid & 31;
    const int wm = wid >> 2, wn = wid & 3;
    const int row0 = blockIdx.x * BM;
    const int colW = blockIdx.y * 128;
    const int z = blockIdx.z;
    const int g0 = (tid & 1) * 4;
    const int arow = tid >> 1;               // BM=128: 0..127; BM=64: valid for tid<128
    const int kchunk0 = (MODE == 5) ? z * Sloc : 0;
    if (MODE == 3 || MODE == 4) Bpk += (size_t)z * Sloc * Nbr * 8;

    int nbrow;
    {
        int p = row0 + (BM == 128 ? arow : (arow & 63));
        if (p >= Mtot) p = Mtot - 1;
        if (MODE == 5) {
            int b = p / 392, q = p % 392;
            int t = q / 196, rem = q % 196, h = rem / 14, w = rem % 14;
            nbrow = (b * 4 + t) * 256 + h * 16 + w;
        } else {
            nbrow = (p >= Ma) ? Ma - 1 : p;
        }
    }
    const uint32_t rbase = (uint32_t)(arow * 128 + g0 * 16);
    const uint32_t rbaseA = (uint32_t)((BM == 128 ? arow : (arow & 63)) * 128 + g0 * 16);

    auto issue = [&](int s, int buf) {
        int sg = kchunk0 + s;
        uint32_t sb = smb + (uint32_t)buf * STRIDE;
        if (BM == 128 || tid < 128) {
            const uint4* asrc;
            if (MODE == 5) {
                int rk = sg >> 4, cc = sg & 15;
                int dt = rk / 9, dh = (rk / 3) % 3, dw = rk - (rk / 3) * 3;
                asrc = Apk + ((size_t)cc * Ma + nbrow + dt * 256 + dh * 16 + dw) * 8 + g0;
            } else {
                asrc = Apk + ((size_t)sg * Ma + nbrow) * 8 + g0;
            }
#pragma unroll
            for (int g = 0; g < 4; g++) {
                uint32_t off = swz(rbaseA + g * 16);
                CP16(sb + off, asrc + g);
            }
        }
        const uint4* bsrc = Bpk + ((size_t)sg * Nbr + colW + arow) * 8 + g0;
#pragma unroll
        for (int g = 0; g < 4; g++) {
            uint32_t off = swz(rbase + g * 16);
            CP16(sb + ABYTES + off, bsrc + g);
        }
        CPCOMMIT();
    };

    float acc[MT][4][4];
#pragma unroll
    for (int i = 0; i < MT; i++)
#pragma unroll
        for (int j = 0; j < 4; j++)
#pragma unroll
            for (int e = 0; e < 4; e++) acc[i][j][e] = 0.f;

    issue(0, 0);
    issue(1, 1);

    const int q = lane >> 3, rl = lane & 7;
    for (int s = 0; s < Sloc; s++) {
        if (s + 1 < Sloc) { CPWAIT(1); } else { CPWAIT(0); }
        __syncthreads();
        if (s + 2 < Sloc) issue(s + 2, (s + 2) % 3);
        const uint32_t aB = smb + (uint32_t)(s % 3) * STRIDE;
        const uint32_t bB = aB + ABYTES;
#pragma unroll
        for (int ks = 0; ks < 4; ks++) {
            uint32_t ah[MT][4];
            uint32_t ao = swz((uint32_t)((wm * (BM / 2) + (q & 1) * 8 + rl) * 128 + ks * 32 + (q >> 1) * 16));
#pragma unroll
            for (int mt = 0; mt < MT; mt++)
                LDSM4(ah[mt][0], ah[mt][1], ah[mt][2], ah[mt][3], aB + ao + mt * 2048);
            uint32_t bo = swz((uint32_t)((wn * 32 + (q >> 1) * 8 + rl) * 128 + ks * 32 + (q & 1) * 16));
#pragma unroll
            for (int pt = 0; pt < 2; pt++) {
                uint32_t bh[4];
                LDSM4(bh[0], bh[1], bh[2], bh[3], bB + bo + pt * 2048);
#pragma unroll
                for (int mt = 0; mt < MT; mt++) {
                    MMA(acc[mt][2 * pt],     ah[mt], bh[0], bh[1]);
                    MMA(acc[mt][2 * pt + 1], ah[mt], bh[2], bh[3]);
                }
            }
        }
    }

    // epilogue (coalesced float2 per lane-quad)
#pragma unroll
    for (int mt = 0; mt < MT; mt++) {
#pragma unroll
        for (int nt = 0; nt < 4; nt++) {
            int f = colW + wn * 32 + nt * 8 + 2 * (lane & 3);
            float b0 = 0.f, b1 = 0.f;
            if (MODE == 1 || MODE == 3 || MODE == 4) { b0 = bias[f]; b1 = bias[f + 1]; }
#pragma unroll
            for (int hh = 0; hh < 2; hh++) {
                int pos = row0 + wm * (BM / 2) + mt * 16 + (lane >> 2) + hh * 8;
                if (pos >= Mtot) continue;
                float v0 = acc[mt][nt][hh * 2], v1 = acc[mt][nt][hh * 2 + 1];
                if (MODE == 0) {
                    *reinterpret_cast<float2*>(&C[(size_t)pos * ldc + f]) = make_float2(v0, v1);
                } else if (MODE == 1) {
                    float2 xv = *reinterpret_cast<const float2*>(&xin[(size_t)pos * ldc + f]);
                    *reinterpret_cast<float2*>(&C[(size_t)pos * ldc + f]) =
                        make_float2(xv.x + fmaxf(v0 + b0, 0.f), xv.y + fmaxf(v1 + b1, 0.f));
                } else if (MODE == 5) {
                    atomicAdd(&C[(size_t)pos * ldc + f], v0);
                    atomicAdd(&C[(size_t)pos * ldc + f + 1], v1);
                } else if (MODE == 3) {
                    int bt = pos >> 6, hw = pos & 63, h = hw >> 3, w = hw & 7;
                    int orow = bt * 256 + (h * 2 + (z >> 1)) * 16 + (w * 2 + (z & 1));
                    *reinterpret_cast<float2*>(&C[(size_t)orow * ldc + f]) =
                        make_float2(fmaxf(v0 + b0, 0.f), fmaxf(v1 + b1, 0.f));
                } else {
                    int bt = pos >> 8, hw = pos & 255, h = hw >> 4, w = hw & 15;
                    int orow = bt * 1024 + (h * 2 + (z >> 1)) * 32 + (w * 2 + (z & 1));
                    *reinterpret_cast<float2*>(&C[(size_t)orow * ldc + f]) =
                        make_float2(v0 + b0, v1 + b1);
                }
            }
        }
    }
}

// ========== misc ==========
__global__ void transpose_ctx(const float* __restrict__ ctx) {
    __shared__ float t[32][33];
    int bt = blockIdx.x, c0 = blockIdx.y * 32, hw0 = blockIdx.z * 32;
    int tx = threadIdx.x, ty = threadIdx.y;
    for (int i = ty; i < 32; i += 8)
        t[i][tx] = ctx[((size_t)bt * 1024 + c0 + i) * 256 + hw0 + tx];
    __syncthreads();
    for (int i = ty; i < 32; i += 8)
        g_x[((size_t)bt * 256 + hw0 + i) * 1024 + c0 + tx] = t[tx][i];
}
__global__ void pack_frame(const float* __restrict__ fr) {
    __shared__ float t[32][33];
    int bt = blockIdx.x, c0 = blockIdx.y * 32, hw0 = blockIdx.z * 32;
    int tx = threadIdx.x, ty = threadIdx.y;
    for (int i = ty; i < 32; i += 8)
        t[i][tx] = fr[((size_t)bt * 1024 + c0 + i) * 64 + hw0 + tx];
    __syncthreads();
    for (int i = ty; i < 32; i += 8)
        g_fb[((size_t)bt * 64 + hw0 + i) * 1024 + c0 + tx] = t[tx][i];
}
__global__ void zero_kernel(float* p, int n) {
    int i = blockIdx.x * blockDim.x + threadIdx.x;
    if (i < n) p[i] = 0.f;
}
__global__ void bn_reduce(const float* __restrict__ y) {
    int c4 = threadIdx.x;
    const float4* y4 = reinterpret_cast<const float4*>(y);
    float4 s = make_float4(0, 0, 0, 0), q = make_float4(0, 0, 0, 0);
    int n0 = blockIdx.x * 32;
    for (int n = n0; n < n0 + 32; n++) {
        float4 v = y4[(size_t)n * 256 + c4];
        s.x += v.x; s.y += v.y; s.z += v.z; s.w += v.w;
        q.x += v.x * v.x; q.y += v.y * v.y; q.z += v.z * v.z; q.w += v.w * v.w;
    }
    atomicAdd(&g_bns[c4 * 4 + 0], s.x); atomicAdd(&g_bns[c4 * 4 + 1], s.y);
    atomicAdd(&g_bns[c4 * 4 + 2], s.z); atomicAdd(&g_bns[c4 * 4 + 3], s.w);
    atomicAdd(&g_bns[1024 + c4 * 4 + 0], q.x); atomicAdd(&g_bns[1024 + c4 * 4 + 1], q.y);
    atomicAdd(&g_bns[1024 + c4 * 4 + 2], q.z); atomicAdd(&g_bns[1024 + c4 * 4 + 3], q.w);
}
// BN apply, writes fp32 x AND packed fp16 qx
__global__ void bn_apply(const float* __restrict__ y, float* __restrict__ xo,
                         uint32_t* __restrict__ qdst,
                         const float* __restrict__ gm, const float* __restrict__ bt) {
    int idx = blockIdx.x * 256 + threadIdx.x;
    int n = idx >> 8, c4 = idx & 255;
    float4 v = reinterpret_cast<const float4*>(y)[idx];
    float4 s = reinterpret_cast<const float4*>(g_bns)[c4];
    float4 q = reinterpret_cast<const float4*>(g_bns + 1024)[c4];
    float4 g = reinterpret_cast<const float4*>(gm)[c4];
    float4 b = reinterpret_cast<const float4*>(bt)[c4];
    const float in = 1.f / NTOT;
    float mx = s.x * in, my = s.y * in, mz = s.z * in, mw = s.w * in;
    float4 r;
    r.x = (v.x - mx) * rsqrtf(q.x * in - mx * mx + 1e-5f) * g.x + b.x;
    r.y = (v.y - my) * rsqrtf(q.y * in - my * my + 1e-5f) * g.y + b.y;
    r.z = (v.z - mz) * rsqrtf(q.z * in - mz * mz + 1e-5f) * g.z + b.z;
    r.w = (v.w - mw) * rsqrtf(q.w * in - mw * mw + 1e-5f) * g.w + b.w;
    reinterpret_cast<float4*>(xo)[idx] = r;
    size_t base = (((size_t)(c4 >> 4) * NTOT + n) * 8 + ((c4 >> 1) & 7)) * 4 + (c4 & 1) * 2;
    qdst[base] = pk2(r.y, r.x);
    qdst[base + 1] = pk2(r.w, r.z);
}
__global__ void goalpre_kernel(const float* __restrict__ tb) {
    int b = blockIdx.x, f = threadIdx.x;
    float bias = tb[f], s = 0.f;
    for (int p = b * 392; p < (b + 1) * 392; p++)
        s += fmaxf(g_conv[(size_t)p * 512 + f] + bias, 0.f);
    g_gp[b * 512 + f] = s * (1.f / 392.f);
}
__global__ void pack_w1(const float* __restrict__ w) {
    int idx = blockIdx.x * 256 + threadIdx.x;
    int c = idx & 1023, o = idx >> 10;
    float4 v = reinterpret_cast<const float4*>(w)[(size_t)c * 512 + o];
    g_w1t[           o * 1024 + c] = v.x;
    g_w1t[ 524288 +  o * 1024 + c] = v.y;
    g_w1t[1048576 +  o * 1024 + c] = v.z;
    g_w1t[1572864 +  o * 1024 + c] = v.w;
}
__global__ void pack_w2(const float* __restrict__ w) {
    int idx = blockIdx.x * 256 + threadIdx.x;
    int c = idx & 511, o = idx >> 9;
    float4 v = reinterpret_cast<const float4*>(w)[(size_t)c * 512 + o];
    g_w2t[          o * 512 + c] = v.x;
    g_w2t[262144 +  o * 512 + c] = v.y;
    g_w2t[524288 +  o * 512 + c] = v.z;
    g_w2t[786432 +  o * 512 + c] = v.w;
}
__global__ void pe_init() {
    int idx = blockIdx.x * 256 + threadIdx.x;
    int n = idx >> 9, c = idx & 511;
    float ang = (float)n * expf(-0.01798894603890390f * (float)(c & ~1));
    g_pe[idx] = (c & 1) ? cosf(ang) : sinf(ang);
}
__global__ void sg_dot() {
    int bt = blockIdx.x, n0 = blockIdx.y * 64;
    int w = threadIdx.x >> 5, lane = threadIdx.x & 31;
    int b = bt / 6;
    const float4* g4 = reinterpret_cast<const float4*>(&g_gp[b * 512]);
#pragma unroll
    for (int j = 0; j < 8; j++) {
        int n = n0 + w * 8 + j;
        const float4* r4 = reinterpret_cast<const float4*>(&g_s2[((size_t)bt * 1024 + n) * 512]);
        float acc = 0.f;
#pragma unroll
        for (int i = 0; i < 4; i++) {
            float4 v = r4[lane + 32 * i], gg = g4[lane + 32 * i];
            acc += v.x * gg.x + v.y * gg.y + v.z * gg.z + v.w * gg.w;
        }
        for (int o = 16; o > 0; o >>= 1) acc += __shfl_down_sync(0xffffffffu, acc, o);
        if (!lane) g_attn[bt * 1024 + n] = acc;
    }
}
__global__ void softmax_norm() {
    int bt = blockIdx.x, tid = threadIdx.x;
    __shared__ float red[256];
    float v[4];
#pragma unroll
    for (int i = 0; i < 4; i++) v[i] = g_attn[bt * 1024 + tid + i * 256];
    float m = fmaxf(fmaxf(v[0], v[1]), fmaxf(v[2], v[3]));
    red[tid] = m; __syncthreads();
    for (int o = 128; o > 0; o >>= 1) { if (tid < o) red[tid] = fmaxf(red[tid], red[tid + o]); __syncthreads(); }
    m = red[0]; __syncthreads();
    float s = 0.f;
#pragma unroll
    for (int i = 0; i < 4; i++) { v[i] = expf(v[i] - m); s += v[i]; }
    red[tid] = s; __syncthreads();
    for (int o = 128; o > 0; o >>= 1) { if (tid < o) red[tid] += red[tid + o]; __syncthreads(); }
    float inv = 1.f / red[0];
#pragma unroll
    for (int i = 0; i < 4; i++) g_attn[bt * 1024 + tid + i * 256] = v[i] * inv;
}
__global__ void sga_kernel() {
    int bt = blockIdx.x, n0 = blockIdx.y * 128, c2 = threadIdx.x;
    float a0 = 0.f, a1 = 0.f;
    for (int n = n0; n < n0 + 128; n++) {
        float at = g_attn[bt * 1024 + n];
        float2 s = *reinterpret_cast<const float2*>(&g_s2[((size_t)bt * 1024 + n) * 512 + c2 * 2]);
        float2 p = *reinterpret_cast<const float2*>(&g_pe[(size_t)n * 512 + c2 * 2]);
        a0 += at * (s.x + p.x); a1 += at * (s.y + p.y);
    }
    atomicAdd(&g_sga[bt * 512 + c2 * 2], a0);
    atomicAdd(&g_sga[bt * 512 + c2 * 2 + 1], a1);
}
__global__ void head_kernel(const float* __restrict__ in,
                            const float* __restrict__ W1, const float* __restrict__ b1,
                            const float* __restrict__ W2, const float* __restrict__ b2,
                            float* __restrict__ out) {
    int r = blockIdx.x, j = threadIdx.x;
    __shared__ float xin[512], t[512];
    xin[j] = in[r * 512 + j];
    __syncthreads();
    float acc = b1[j];
    const float* w = W1 + (size_t)j * 512;
    for (int k = 0; k < 512; k++) acc += xin[k] * w[k];
    t[j] = fmaxf(acc, 0.f);
    __syncthreads();
    if (j < OUTD) {
        float a2 = b2[j];
        const float* w2 = W2 + (size_t)j * 512;
        for (int k = 0; k < 512; k++) a2 += t[k] * w2[k];
        out[r * OUTD + j] = a2;
    }
}

// ---------- launch ----------
extern "C" void kernel_launch(void* const* d_in, const int* in_sizes, int n_in,
                              void* d_out, int out_size) {
    const float* ctx   = (const float*)d_in[0];
    const float* frame = (const float*)d_in[1];
    const float* nl_vw[2]   = { (const float*)d_in[4],  (const float*)d_in[11] };
    const float* nl_ow[2]   = { (const float*)d_in[5],  (const float*)d_in[12] };
    const float* nl_ob[2]   = { (const float*)d_in[6],  (const float*)d_in[13] };
    const float* nl_g[2]    = { (const float*)d_in[7],  (const float*)d_in[14] };
    const float* nl_beta[2] = { (const float*)d_in[8],  (const float*)d_in[15] };
    const float* tp_w  = (const float*)d_in[16];
    const float* tp_b  = (const float*)d_in[17];
    const float* up1_w = (const float*)d_in[18];
    const float* up1_b = (const float*)d_in[19];
    const float* up2_w = (const float*)d_in[20];
    const float* up2_b = (const float*)d_in[21];
    float* out = (float*)d_out;

    float *px, *py, *pv, *pconv, *pw1t, *pw2t, *ps1, *ps2, *pfb, *pgp, *psga, *pbns;
    cudaGetSymbolAddress((void**)&px, g_x);
    cudaGetSymbolAddress((void**)&py, g_y);
    cudaGetSymbolAddress((void**)&pv, g_v);
    cudaGetSymbolAddress((void**)&pconv, g_conv);
    cudaGetSymbolAddress((void**)&pw1t, g_w1t);
    cudaGetSymbolAddress((void**)&pw2t, g_w2t);
    cudaGetSymbolAddress((void**)&ps1, g_s1);
    cudaGetSymbolAddress((void**)&ps2, g_s2);
    cudaGetSymbolAddress((void**)&pfb, g_fb);
    cudaGetSymbolAddress((void**)&pgp, g_gp);
    cudaGetSymbolAddress((void**)&psga, g_sga);
    cudaGetSymbolAddress((void**)&pbns, g_bns);
    uint4 *qx, *qv, *qfb, *qs1, *qwc, *qvw0, *qvw1, *qow0, *qow1, *qw1, *qw2;
    cudaGetSymbolAddress((void**)&qx, pk_x);
    cudaGetSymbolAddress((void**)&qv, pk_v);
    cudaGetSymbolAddress((void**)&qfb, pk_fb);
    cudaGetSymbolAddress((void**)&qs1, pk_s1);
    cudaGetSymbolAddress((void**)&qwc, pk_wc);
    cudaGetSymbolAddress((void**)&qvw0, pk_vw); qvw1 = qvw0 + 16 * FFD * 8;
    cudaGetSymbolAddress((void**)&qow0, pk_ow); qow1 = qow0 + 8 * CIN * 8;
    cudaGetSymbolAddress((void**)&qw1, pk_w1);
    cudaGetSymbolAddress((void**)&qw2, pk_w2);
    uint4* qvw[2] = { qvw0, qvw1 };
    uint4* qow[2] = { qow0, qow1 };

    cudaFuncSetAttribute((const void*)tc_gemm<0, 128>, cudaFuncAttributeMaxDynamicSharedMemorySize, SM128);
    cudaFuncSetAttribute((const void*)tc_gemm<1, 128>, cudaFuncAttributeMaxDynamicSharedMemorySize, SM128);
    cudaFuncSetAttribute((const void*)tc_gemm<3, 64>,  cudaFuncAttributeMaxDynamicSharedMemorySize, SM64);
    cudaFuncSetAttribute((const void*)tc_gemm<4, 128>, cudaFuncAttributeMaxDynamicSharedMemorySize, SM128);
    cudaFuncSetAttribute((const void*)tc_gemm<5, 128>, cudaFuncAttributeMaxDynamicSharedMemorySize, SM128);

    // launches 1-3 are the V-GEMM deps, so #4 (profiled) is tc_gemm<0,128>
    transpose_ctx<<<dim3(16, 32, 8), dim3(32, 8)>>>(ctx);                    // 1
    pack_act<<<(NTOT * CIN / 8) / 256, 256>>>(px, qx, NTOT, 1024);           // 2
    pack_act<<<(512 * 1024 / 8) / 256, 256>>>(nl_vw[0], qvw[0], 512, 1024);  // 3
    tc_gemm<0, 128><<<dim3(32, 4), 256, SM128>>>(                            // 4 (profiled)
        qx, qvw[0], pv, NTOT, NTOT, 512, 16, 512, nullptr, nullptr);

    pack_act<<<(1024 * 512 / 8) / 256, 256>>>(nl_ow[0], qow[0], 1024, 512);
    pack_act<<<(512 * 1024 / 8) / 256, 256>>>(nl_vw[1], qvw[1], 512, 1024);
    pack_act<<<(1024 * 512 / 8) / 256, 256>>>(nl_ow[1], qow[1], 1024, 512);
    pe_init<<<2048, 256>>>();
    pack_frame<<<dim3(24, 32, 2), dim3(32, 8)>>>(frame);
    pack_act<<<(1536 * 1024 / 8) / 256, 256>>>(pfb, qfb, 1536, 1024);
    pack_w1<<<2048, 256>>>(up1_w);
    for (int kl = 0; kl < 4; kl++)
        pack_act<<<(512 * 1024 / 8) / 256, 256>>>(pw1t + (size_t)kl * 524288,
                                                  qw1 + (size_t)kl * 16 * 512 * 8, 512, 1024);
    pack_w2<<<1024, 256>>>(up2_w);
    for (int kl = 0; kl < 4; kl++)
        pack_act<<<(512 * 512 / 8) / 256, 256>>>(pw2t + (size_t)kl * 262144,
                                                 qw2 + (size_t)kl * 8 * 512 * 8, 512, 512);
    pack_wconv<<<dim3(512, 4), 256>>>(tp_w);
    zero_kernel<<<(PCONV * 512 + 255) / 256, 256>>>(pconv, PCONV * 512);

    for (int l = 0; l < 2; l++) {
        if (l == 1)
            tc_gemm<0, 128><<<dim3(32, 4), 256, SM128>>>(
                qx, qvw[1], pv, NTOT, NTOT, 512, 16, 512, nullptr, nullptr);
        pack_act<<<(NTOT * 512 / 8) / 256, 256>>>(pv, qv, NTOT, 512);
        tc_gemm<1, 128><<<dim3(32, 8), 256, SM128>>>(
            qv, qow[l], py, NTOT, NTOT, 1024, 8, 1024, nl_ob[l], px);
        zero_kernel<<<8, 256>>>(pbns, 2048);
        bn_reduce<<<128, 256>>>(py);
        bn_apply<<<4096, 256>>>(py, px, (uint32_t*)qx, nl_g[l], nl_beta[l]);
    }

    // conv3d: packed A gathered from pk_x, z = 16 K-splits of 27 chunks (432 total)
    tc_gemm<5, 128><<<dim3(13, 4, 16), 256, SM128>>>(
        qx, qwc, pconv, PCONV, NTOT, 512, 27, 512, nullptr, nullptr);
    goalpre_kernel<<<4, 512>>>(tp_b);

    tc_gemm<3, 64><<<dim3(24, 4, 4), 256, SM64>>>(
        qfb, qw1, ps1, 1536, 1536, 512, 16, 512, up1_b, nullptr);
    pack_act<<<(6144 * 512 / 8) / 256, 256>>>(ps1, qs1, 6144, 512);
    tc_gemm<4, 128><<<dim3(48, 4, 4), 256, SM128>>>(
        qs1, qw2, ps2, 6144, 6144, 512, 8, 512, up2_b, nullptr);

    sg_dot<<<dim3(24, 16), 256>>>();
    softmax_norm<<<24, 256>>>();
    zero_kernel<<<48, 256>>>(psga, BT * 512);
    sga_kernel<<<dim3(24, 8), 256>>>();

    head_kernel<<<4, 512>>>(pgp, (const float*)d_in[22], (const float*)d_in[23],
                            (const float*)d_in[24], (const float*)d_in[25], out);
    head_kernel<<<BT, 512>>>(psga, (const float*)d_in[26], (const float*)d_in[27],
                             (const float*)d_in[28], (const float*)d_in[29], out + 4 * OUTD);
}

// round 14
// speedup vs baseline: 1.0893x; 1.0272x over previous
#include <cuda_runtime.h>
#include <cuda_fp16.h>
#include <cstdint>
#include <math.h>

#define CIN   1024
#define FFD   512
#define OUTD  128
#define NTOT  4096
#define KCONV 27648
#define PCONV 1568
#define BT    24
#define NS    1024
#define SM64  73728    // 3 x (8KB A + 16KB B)
#define SM128 98304    // 3 x (16KB A + 16KB B)

// ---------- fp32 scratch ----------
__device__ float g_x[(size_t)NTOT * CIN];
__device__ float g_y[(size_t)NTOT * CIN];
__device__ float g_conv[(size_t)PCONV * FFD];
__device__ float g_gp[4 * FFD];
__device__ float g_s2[(size_t)(BT * 1024) * FFD];
__device__ float g_pe[(size_t)NS * FFD];
__device__ float g_attn[BT * NS];
__device__ float g_sga[BT * FFD];
__device__ float g_bns[2048];
// ---------- packed fp16 operands: [chunk of 64 K][row][128B = 64 fp16] ----------
__device__ uint4 pk_x[16 * NTOT * 8];
__device__ uint4 pk_v[8 * NTOT * 8];
__device__ uint4 pk_fb[16 * (BT * 64) * 8];
__device__ uint4 pk_s1[8 * (BT * 1024) * 8];
__device__ uint4 pk_wc[432 * FFD * 8];
__device__ uint4 pk_vw[2][16 * FFD * 8];
__device__ uint4 pk_ow[2][8 * CIN * 8];
__device__ uint4 pk_w1[4 * 16 * FFD * 8];
__device__ uint4 pk_w2[4 * 8 * FFD * 8];

// ---------- helpers ----------
__device__ __forceinline__ uint32_t smem_u32(const void* p) {
    uint32_t a;
    asm("{ .reg .u64 t; cvta.to.shared.u64 t, %1; cvt.u32.u64 %0, t; }" : "=r"(a) : "l"(p));
    return a;
}
#define LDSM4(r0, r1, r2, r3, addr) \
    asm volatile("ldmatrix.sync.aligned.m8n8.x4.shared.b16 {%0,%1,%2,%3}, [%4];" \
        : "=r"(r0), "=r"(r1), "=r"(r2), "=r"(r3) : "r"(addr))
#define MMA(c, a, b0, b1) \
    asm volatile("mma.sync.aligned.m16n8k16.row.col.f32.f16.f16.f32 " \
        "{%0,%1,%2,%3},{%4,%5,%6,%7},{%8,%9},{%0,%1,%2,%3};" \
        : "+f"((c)[0]), "+f"((c)[1]), "+f"((c)[2]), "+f"((c)[3]) \
        : "r"((a)[0]), "r"((a)[1]), "r"((a)[2]), "r"((a)[3]), "r"(b0), "r"(b1))
#define CP16(dst, src) \
    asm volatile("cp.async.cg.shared.global [%0], [%1], 16;" :: "r"(dst), "l"(src))
#define CPCOMMIT() asm volatile("cp.async.commit_group;" ::: "memory")
#define CPWAIT(n)  asm volatile("cp.async.wait_group %0;" :: "n"(n) : "memory")

__device__ __forceinline__ uint32_t pk2(float hi, float lo) {   // {hi:lo} fp16x2
    uint32_t r;
    asm("cvt.rn.f16x2.f32 %0, %1, %2;" : "=r"(r) : "f"(hi), "f"(lo));
    return r;
}
__device__ __forceinline__ uint4 pack8(float4 a, float4 b) {
    uint4 h;
    h.x = pk2(a.y, a.x); h.y = pk2(a.w, a.z);
    h.z = pk2(b.y, b.x); h.w = pk2(b.w, b.z);
    return h;
}
__device__ __forceinline__ uint32_t swz(uint32_t o) { return o ^ ((o >> 3) & 0x70u); }

// fp32 [M][K] -> packed fp16 [K/64][M][128B]
__global__ void pack_act(const float* __restrict__ src, uint4* __restrict__ dst, int M, int K) {
    int idx = blockIdx.x * 256 + threadIdx.x;
    int kg = K >> 3;
    int row = idx / kg, u = idx - row * kg;
    int chunk = u >> 3, g = u & 7;
    const float* s = src + (size_t)row * K + u * 8;
    float4 a = *(const float4*)s, b = *(const float4*)(s + 4);
    dst[((size_t)chunk * M + row) * 8 + g] = pack8(a, b);
}
// conv weights (FF, CIN, 27) -> packed fp16 [chunk = rk*16 + c/64][512][128B]
__global__ void pack_wconv(const float* __restrict__ w) {   // grid (512, 4), 256 thr
    __shared__ float st[27][260];
    int f = blockIdx.x, c0 = blockIdx.y * 256;
    const float* src = w + (size_t)f * KCONV + (size_t)c0 * 27;
    for (int i = threadIdx.x; i < 27 * 256; i += 256) {
        int c = i / 27, r = i - c * 27;
        st[r][c] = src[i];
    }
    __syncthreads();
    for (int u = threadIdx.x; u < 27 * 32; u += 256) {
        int r = u >> 5, grp = u & 31;
        const float* p = &st[r][grp * 8];
        float4 a = make_float4(p[0], p[1], p[2], p[3]);
        float4 b = make_float4(p[4], p[5], p[6], p[7]);
        int chunk = r * 16 + (c0 >> 6) + (grp >> 3);
        pk_wc[((size_t)chunk * FFD + f) * 8 + (grp & 7)] = pack8(a, b);
    }
}
// ConvTranspose weights [Cdim][512][4 kl] -> 4 packed arrays [Cdim/64][512][8]
__global__ void pack_wd(const float* __restrict__ w, uint4* __restrict__ dst, int Cdim) {
    __shared__ float st[4][32][65];
    int c0 = blockIdx.x * 32, o0 = blockIdx.y * 64;
    for (int t = threadIdx.x; t < 2048; t += 256) {
        int c = t >> 6, o = t & 63;
        float4 v = reinterpret_cast<const float4*>(w)[(size_t)(c0 + c) * 512 + o0 + o];
        st[0][c][o] = v.x; st[1][c][o] = v.y; st[2][c][o] = v.z; st[3][c][o] = v.w;
    }
    __syncthreads();
    size_t kls = (size_t)(Cdim >> 6) * 512 * 8;
    for (int t = threadIdx.x; t < 1024; t += 256) {
        int kl = t >> 8, o = (t >> 2) & 63, g = t & 3;
        float4 a, b;
        a.x = st[kl][g * 8 + 0][o]; a.y = st[kl][g * 8 + 1][o];
        a.z = st[kl][g * 8 + 2][o]; a.w = st[kl][g * 8 + 3][o];
        b.x = st[kl][g * 8 + 4][o]; b.y = st[kl][g * 8 + 5][o];
        b.z = st[kl][g * 8 + 6][o]; b.w = st[kl][g * 8 + 7][o];
        int chunk = c0 >> 6, gb = ((c0 & 63) >> 3) + g;
        dst[kl * kls + ((size_t)chunk * 512 + o0 + o) * 8 + gb] = pack8(a, b);
    }
}

// ===== cp.async 3-stage warp-MMA fp16 GEMM, tile BM x 128N, warps 2m x 4n =====
// MODE 0 packed-fp16 out | 1 xin+relu(v+bias) fp32 | 3 up1 scatter relu packed-fp16 |
// MODE 4 up2 scatter fp32 | 5 conv atomicAdd.   For MODE 0/3, ldc = packed M.
template <int MODE, int BM>
__global__ void __launch_bounds__(256, 2) tc_gemm(
    const uint4* __restrict__ Apk, const uint4* __restrict__ Bpk, float* __restrict__ C,
    int Mtot, int Ma, int Nbr, int Sloc, int ldc,
    const float* __restrict__ bias, const float* __restrict__ xin)
{
    constexpr int MT = BM / 32;
    constexpr uint32_t ABYTES = BM * 128;
    constexpr uint32_t STRIDE = ABYTES + 16384;
    extern __shared__ char dsm[];
    const uint32_t smb = smem_u32(dsm);
    const int tid = threadIdx.x, wid = tid >> 5, lane = tid & 31;
    const int wm = wid >> 2, wn = wid & 3;
    const int row0 = blockIdx.x * BM;
    const int colW = blockIdx.y * 128;
    const int z = blockIdx.z;
    const int g0 = (tid & 1) * 4;
    const int arow = tid >> 1;
    const int kchunk0 = (MODE == 5) ? z * Sloc : 0;
    if (MODE == 3 || MODE == 4) Bpk += (size_t)z * Sloc * Nbr * 8;

    int nbrow;
    {
        int p = row0 + (BM == 128 ? arow : (arow & 63));
        if (p >= Mtot) p = Mtot - 1;
        if (MODE == 5) {
            int b = p / 392, q = p % 392;
            int t = q / 196, rem = q % 196, h = rem / 14, w = rem % 14;
            nbrow = (b * 4 + t) * 256 + h * 16 + w;
        } else {
            nbrow = (p >= Ma) ? Ma - 1 : p;
        }
    }
    const uint32_t rbase = (uint32_t)(arow * 128 + g0 * 16);
    const uint32_t rbaseA = (uint32_t)((BM == 128 ? arow : (arow & 63)) * 128 + g0 * 16);

    auto issue = [&](int s, int buf) {
        int sg = kchunk0 + s;
        uint32_t sb = smb + (uint32_t)buf * STRIDE;
        if (BM == 128 || tid < 128) {
            const uint4* asrc;
            if (MODE == 5) {
                int rk = sg >> 4, cc = sg & 15;
                int dt = rk / 9, dh = (rk / 3) % 3, dw = rk - (rk / 3) * 3;
                asrc = Apk + ((size_t)cc * Ma + nbrow + dt * 256 + dh * 16 + dw) * 8 + g0;
            } else {
                asrc = Apk + ((size_t)sg * Ma + nbrow) * 8 + g0;
            }
#pragma unroll
            for (int g = 0; g < 4; g++) {
                uint32_t off = swz(rbaseA + g * 16);
                CP16(sb + off, asrc + g);
            }
        }
        const uint4* bsrc = Bpk + ((size_t)sg * Nbr + colW + arow) * 8 + g0;
#pragma unroll
        for (int g = 0; g < 4; g++) {
            uint32_t off = swz(rbase + g * 16);
            CP16(sb + ABYTES + off, bsrc + g);
        }
        CPCOMMIT();
    };

    float acc[MT][4][4];
#pragma unroll
    for (int i = 0; i < MT; i++)
#pragma unroll
        for (int j = 0; j < 4; j++)
#pragma unroll
            for (int e = 0; e < 4; e++) acc[i][j][e] = 0.f;

    issue(0, 0);
    issue(1, 1);

    const int q = lane >> 3, rl = lane & 7;
    for (int s = 0; s < Sloc; s++) {
        if (s + 1 < Sloc) { CPWAIT(1); } else { CPWAIT(0); }
        __syncthreads();
        if (s + 2 < Sloc) issue(s + 2, (s + 2) % 3);
        const uint32_t aB = smb + (uint32_t)(s % 3) * STRIDE;
        const uint32_t bB = aB + ABYTES;
#pragma unroll
        for (int ks = 0; ks < 4; ks++) {
            uint32_t ah[MT][4];
            uint32_t ao = swz((uint32_t)((wm * (BM / 2) + (q & 1) * 8 + rl) * 128 + ks * 32 + (q >> 1) * 16));
#pragma unroll
            for (int mt = 0; mt < MT; mt++)
                LDSM4(ah[mt][0], ah[mt][1], ah[mt][2], ah[mt][3], aB + ao + mt * 2048);
            uint32_t bo = swz((uint32_t)((wn * 32 + (q >> 1) * 8 + rl) * 128 + ks * 32 + (q & 1) * 16));
#pragma unroll
            for (int pt = 0; pt < 2; pt++) {
                uint32_t bh[4];
                LDSM4(bh[0], bh[1], bh[2], bh[3], bB + bo + pt * 2048);
#pragma unroll
                for (int mt = 0; mt < MT; mt++) {
                    MMA(acc[mt][2 * pt],     ah[mt], bh[0], bh[1]);
                    MMA(acc[mt][2 * pt + 1], ah[mt], bh[2], bh[3]);
                }
            }
        }
    }

    // epilogue
#pragma unroll
    for (int mt = 0; mt < MT; mt++) {
#pragma unroll
        for (int nt = 0; nt < 4; nt++) {
            int f = colW + wn * 32 + nt * 8 + 2 * (lane & 3);
            float b0 = 0.f, b1 = 0.f;
            if (MODE == 1 || MODE == 3 || MODE == 4) { b0 = bias[f]; b1 = bias[f + 1]; }
#pragma unroll
            for (int hh = 0; hh < 2; hh++) {
                int pos = row0 + wm * (BM / 2) + mt * 16 + (lane >> 2) + hh * 8;
                if (pos >= Mtot) continue;
                float v0 = acc[mt][nt][hh * 2], v1 = acc[mt][nt][hh * 2 + 1];
                if (MODE == 0) {           // packed fp16 out; ldc = packed M
                    reinterpret_cast<uint32_t*>(C)[
                        ((size_t)(f >> 6) * ldc + pos) * 32 + ((f & 63) >> 1)] = pk2(v1, v0);
                } else if (MODE == 1) {
                    float2 xv = *reinterpret_cast<const float2*>(&xin[(size_t)pos * ldc + f]);
                    *reinterpret_cast<float2*>(&C[(size_t)pos * ldc + f]) =
                        make_float2(xv.x + fmaxf(v0 + b0, 0.f), xv.y + fmaxf(v1 + b1, 0.f));
                } else if (MODE == 5) {
                    atomicAdd(&C[(size_t)pos * ldc + f], v0);
                    atomicAdd(&C[(size_t)pos * ldc + f + 1], v1);
                } else if (MODE == 3) {    // up1 scatter, packed fp16 out; ldc = packed M
                    int bt = pos >> 6, hw = pos & 63, h = hw >> 3, w = hw & 7;
                    int orow = bt * 256 + (h * 2 + (z >> 1)) * 16 + (w * 2 + (z & 1));
                    float s0 = fmaxf(v0 + b0, 0.f), s1v = fmaxf(v1 + b1, 0.f);
                    reinterpret_cast<uint32_t*>(C)[
                        ((size_t)(f >> 6) * ldc + orow) * 32 + ((f & 63) >> 1)] = pk2(s1v, s0);
                } else {
                    int bt = pos >> 8, hw = pos & 255, h = hw >> 4, w = hw & 15;
                    int orow = bt * 1024 + (h * 2 + (z >> 1)) * 32 + (w * 2 + (z & 1));
                    *reinterpret_cast<float2*>(&C[(size_t)orow * ldc + f]) =
                        make_float2(v0 + b0, v1 + b1);
                }
            }
        }
    }
}

// ========== misc ==========
// context transpose -> fp32 g_x AND packed pk_x
__global__ void transpose_ctx(const float* __restrict__ ctx) {
    __shared__ float t[32][33];
    int bt = blockIdx.x, c0 = blockIdx.y * 32, hw0 = blockIdx.z * 32;
    int tx = threadIdx.x, ty = threadIdx.y;
    for (int i = ty; i < 32; i += 8)
        t[i][tx] = ctx[((size_t)bt * 1024 + c0 + i) * 256 + hw0 + tx];
    __syncthreads();
    for (int i = ty; i < 32; i += 8)
        g_x[((size_t)bt * 256 + hw0 + i) * 1024 + c0 + tx] = t[tx][i];
    int tid = ty * 32 + tx;
    if (tid < 128) {
        int ii = tid >> 2, j = tid & 3;
        int n = bt * 256 + hw0 + ii;
        float4 a, b;
        a.x = t[j * 8 + 0][ii]; a.y = t[j * 8 + 1][ii]; a.z = t[j * 8 + 2][ii]; a.w = t[j * 8 + 3][ii];
        b.x = t[j * 8 + 4][ii]; b.y = t[j * 8 + 5][ii]; b.z = t[j * 8 + 6][ii]; b.w = t[j * 8 + 7][ii];
        int chunk = c0 >> 6, gb = ((c0 & 63) >> 3) + j;
        pk_x[((size_t)chunk * NTOT + n) * 8 + gb] = pack8(a, b);
    }
}
// frame -> packed pk_fb only
__global__ void pack_frame(const float* __restrict__ fr) {
    __shared__ float t[32][33];
    int bt = blockIdx.x, c0 = blockIdx.y * 32, hw0 = blockIdx.z * 32;
    int tx = threadIdx.x, ty = threadIdx.y;
    for (int i = ty; i < 32; i += 8)
        t[i][tx] = fr[((size_t)bt * 1024 + c0 + i) * 64 + hw0 + tx];
    __syncthreads();
    int tid = ty * 32 + tx;
    if (tid < 128) {
        int ii = tid >> 2, j = tid & 3;
        int n = bt * 64 + hw0 + ii;
        float4 a, b;
        a.x = t[j * 8 + 0][ii]; a.y = t[j * 8 + 1][ii]; a.z = t[j * 8 + 2][ii]; a.w = t[j * 8 + 3][ii];
        b.x = t[j * 8 + 4][ii]; b.y = t[j * 8 + 5][ii]; b.z = t[j * 8 + 6][ii]; b.w = t[j * 8 + 7][ii];
        int chunk = c0 >> 6, gb = ((c0 & 63) >> 3) + j;
        pk_fb[((size_t)chunk * (BT * 64) + n) * 8 + gb] = pack8(a, b);
    }
}
__global__ void zero_kernel(float* p, int n) {
    int i = blockIdx.x * blockDim.x + threadIdx.x;
    if (i < n) p[i] = 0.f;
}
__global__ void bn_reduce(const float* __restrict__ y) {
    int c4 = threadIdx.x;
    const float4* y4 = reinterpret_cast<const float4*>(y);
    float4 s = make_float4(0, 0, 0, 0), q = make_float4(0, 0, 0, 0);
    int n0 = blockIdx.x * 32;
    for (int n = n0; n < n0 + 32; n++) {
        float4 v = y4[(size_t)n * 256 + c4];
        s.x += v.x; s.y += v.y; s.z += v.z; s.w += v.w;
        q.x += v.x * v.x; q.y += v.y * v.y; q.z += v.z * v.z; q.w += v.w * v.w;
    }
    atomicAdd(&g_bns[c4 * 4 + 0], s.x); atomicAdd(&g_bns[c4 * 4 + 1], s.y);
    atomicAdd(&g_bns[c4 * 4 + 2], s.z); atomicAdd(&g_bns[c4 * 4 + 3], s.w);
    atomicAdd(&g_bns[1024 + c4 * 4 + 0], q.x); atomicAdd(&g_bns[1024 + c4 * 4 + 1], q.y);
    atomicAdd(&g_bns[1024 + c4 * 4 + 2], q.z); atomicAdd(&g_bns[1024 + c4 * 4 + 3], q.w);
}
// BN apply, writes fp32 x AND packed fp16 qx
__global__ void bn_apply(const float* __restrict__ y, float* __restrict__ xo,
                         uint32_t* __restrict__ qdst,
                         const float* __restrict__ gm, const float* __restrict__ bt) {
    int idx = blockIdx.x * 256 + threadIdx.x;
    int n = idx >> 8, c4 = idx & 255;
    float4 v = reinterpret_cast<const float4*>(y)[idx];
    float4 s = reinterpret_cast<const float4*>(g_bns)[c4];
    float4 q = reinterpret_cast<const float4*>(g_bns + 1024)[c4];
    float4 g = reinterpret_cast<const float4*>(gm)[c4];
    float4 b = reinterpret_cast<const float4*>(bt)[c4];
    const float in = 1.f / NTOT;
    float mx = s.x * in, my = s.y * in, mz = s.z * in, mw = s.w * in;
    float4 r;
    r.x = (v.x - mx) * rsqrtf(q.x * in - mx * mx + 1e-5f) * g.x + b.x;
    r.y = (v.y - my) * rsqrtf(q.y * in - my * my + 1e-5f) * g.y + b.y;
    r.z = (v.z - mz) * rsqrtf(q.z * in - mz * mz + 1e-5f) * g.z + b.z;
    r.w = (v.w - mw) * rsqrtf(q.w * in - mw * mw + 1e-5f) * g.w + b.w;
    reinterpret_cast<float4*>(xo)[idx] = r;
    size_t base = (((size_t)(c4 >> 4) * NTOT + n) * 8 + ((c4 >> 1) & 7)) * 4 + (c4 & 1) * 2;
    qdst[base] = pk2(r.y, r.x);
    qdst[base + 1] = pk2(r.w, r.z);
}
__global__ void goalpre_kernel(const float* __restrict__ tb) {
    int b = blockIdx.x, f = threadIdx.x;
    float bias = tb[f], s = 0.f;
    for (int p = b * 392; p < (b + 1) * 392; p++)
        s += fmaxf(g_conv[(size_t)p * 512 + f] + bias, 0.f);
    g_gp[b * 512 + f] = s * (1.f / 392.f);
}
__global__ void pe_init() {
    int idx = blockIdx.x * 256 + threadIdx.x;
    int n = idx >> 9, c = idx & 511;
    float ang = (float)n * expf(-0.01798894603890390f * (float)(c & ~1));
    g_pe[idx] = (c & 1) ? cosf(ang) : sinf(ang);
}
__global__ void sg_dot() {
    int bt = blockIdx.x, n0 = blockIdx.y * 64;
    int w = threadIdx.x >> 5, lane = threadIdx.x & 31;
    int b = bt / 6;
    const float4* g4 = reinterpret_cast<const float4*>(&g_gp[b * 512]);
#pragma unroll
    for (int j = 0; j < 8; j++) {
        int n = n0 + w * 8 + j;
        const float4* r4 = reinterpret_cast<const float4*>(&g_s2[((size_t)bt * 1024 + n) * 512]);
        float acc = 0.f;
#pragma unroll
        for (int i = 0; i < 4; i++) {
            float4 v = r4[lane + 32 * i], gg = g4[lane + 32 * i];
            acc += v.x * gg.x + v.y * gg.y + v.z * gg.z + v.w * gg.w;
        }
        for (int o = 16; o > 0; o >>= 1) acc += __shfl_down_sync(0xffffffffu, acc, o);
        if (!lane) g_attn[bt * 1024 + n] = acc;
    }
}
__global__ void softmax_norm() {
    int bt = blockIdx.x, tid = threadIdx.x;
    __shared__ float red[256];
    float v[4];
#pragma unroll
    for (int i = 0; i < 4; i++) v[i] = g_attn[bt * 1024 + tid + i * 256];
    float m = fmaxf(fmaxf(v[0], v[1]), fmaxf(v[2], v[3]));
    red[tid] = m; __syncthreads();
    for (int o = 128; o > 0; o >>= 1) { if (tid < o) red[tid] = fmaxf(red[tid], red[tid + o]); __syncthreads(); }
    m = red[0]; __syncthreads();
    float s = 0.f;
#pragma unroll
    for (int i = 0; i < 4; i++) { v[i] = expf(v[i] - m); s += v[i]; }
    red[tid] = s; __syncthreads();
    for (int o = 128; o > 0; o >>= 1) { if (tid < o) red[tid] += red[tid + o]; __syncthreads(); }
    float inv = 1.f / red[0];
#pragma unroll
    for (int i = 0; i < 4; i++) g_attn[bt * 1024 + tid + i * 256] = v[i] * inv;
}
__global__ void sga_kernel() {
    int bt = blockIdx.x, n0 = blockIdx.y * 128, c2 = threadIdx.x;
    float a0 = 0.f, a1 = 0.f;
    for (int n = n0; n < n0 + 128; n++) {
        float at = g_attn[bt * 1024 + n];
        float2 s = *reinterpret_cast<const float2*>(&g_s2[((size_t)bt * 1024 + n) * 512 + c2 * 2]);
        float2 p = *reinterpret_cast<const float2*>(&g_pe[(size_t)n * 512 + c2 * 2]);
        a0 += at * (s.x + p.x); a1 += at * (s.y + p.y);
    }
    atomicAdd(&g_sga[bt * 512 + c2 * 2], a0);
    atomicAdd(&g_sga[bt * 512 + c2 * 2 + 1], a1);
}
__global__ void head_kernel(const float* __restrict__ in,
                            const float* __restrict__ W1, const float* __restrict__ b1,
                            const float* __restrict__ W2, const float* __restrict__ b2,
                            float* __restrict__ out) {
    int r = blockIdx.x, j = threadIdx.x;
    __shared__ float xin[512], t[512];
    xin[j] = in[r * 512 + j];
    __syncthreads();
    float acc = b1[j];
    const float* w = W1 + (size_t)j * 512;
    for (int k = 0; k < 512; k++) acc += xin[k] * w[k];
    t[j] = fmaxf(acc, 0.f);
    __syncthreads();
    if (j < OUTD) {
        float a2 = b2[j];
        const float* w2 = W2 + (size_t)j * 512;
        for (int k = 0; k < 512; k++) a2 += t[k] * w2[k];
        out[r * OUTD + j] = a2;
    }
}

// ---------- launch ----------
extern "C" void kernel_launch(void* const* d_in, const int* in_sizes, int n_in,
                              void* d_out, int out_size) {
    const float* ctx   = (const float*)d_in[0];
    const float* frame = (const float*)d_in[1];
    const float* nl_vw[2]   = { (const float*)d_in[4],  (const float*)d_in[11] };
    const float* nl_ow[2]   = { (const float*)d_in[5],  (const float*)d_in[12] };
    const float* nl_ob[2]   = { (const float*)d_in[6],  (const float*)d_in[13] };
    const float* nl_g[2]    = { (const float*)d_in[7],  (const float*)d_in[14] };
    const float* nl_beta[2] = { (const float*)d_in[8],  (const float*)d_in[15] };
    const float* tp_w  = (const float*)d_in[16];
    const float* tp_b  = (const float*)d_in[17];
    const float* up1_w = (const float*)d_in[18];
    const float* up1_b = (const float*)d_in[19];
    const float* up2_w = (const float*)d_in[20];
    const float* up2_b = (const float*)d_in[21];
    float* out = (float*)d_out;

    float *px, *py, *pconv, *ps2, *pgp, *psga, *pbns;
    cudaGetSymbolAddress((void**)&px, g_x);
    cudaGetSymbolAddress((void**)&py, g_y);
    cudaGetSymbolAddress((void**)&pconv, g_conv);
    cudaGetSymbolAddress((void**)&ps2, g_s2);
    cudaGetSymbolAddress((void**)&pgp, g_gp);
    cudaGetSymbolAddress((void**)&psga, g_sga);
    cudaGetSymbolAddress((void**)&pbns, g_bns);
    uint4 *qx, *qv, *qfb, *qs1, *qwc, *qvw0, *qvw1, *qow0, *qow1, *qw1, *qw2;
    cudaGetSymbolAddress((void**)&qx, pk_x);
    cudaGetSymbolAddress((void**)&qv, pk_v);
    cudaGetSymbolAddress((void**)&qfb, pk_fb);
    cudaGetSymbolAddress((void**)&qs1, pk_s1);
    cudaGetSymbolAddress((void**)&qwc, pk_wc);
    cudaGetSymbolAddress((void**)&qvw0, pk_vw); qvw1 = qvw0 + 16 * FFD * 8;
    cudaGetSymbolAddress((void**)&qow0, pk_ow); qow1 = qow0 + 8 * CIN * 8;
    cudaGetSymbolAddress((void**)&qw1, pk_w1);
    cudaGetSymbolAddress((void**)&qw2, pk_w2);
    uint4* qvw[2] = { qvw0, qvw1 };
    uint4* qow[2] = { qow0, qow1 };

    cudaFuncSetAttribute((const void*)tc_gemm<0, 128>, cudaFuncAttributeMaxDynamicSharedMemorySize, SM128);
    cudaFuncSetAttribute((const void*)tc_gemm<1, 128>, cudaFuncAttributeMaxDynamicSharedMemorySize, SM128);
    cudaFuncSetAttribute((const void*)tc_gemm<3, 64>,  cudaFuncAttributeMaxDynamicSharedMemorySize, SM64);
    cudaFuncSetAttribute((const void*)tc_gemm<4, 128>, cudaFuncAttributeMaxDynamicSharedMemorySize, SM128);
    cudaFuncSetAttribute((const void*)tc_gemm<5, 128>, cudaFuncAttributeMaxDynamicSharedMemorySize, SM128);

    // launches 1-3 are the V-GEMM deps, so #4 (profiled) is tc_gemm<0,128>
    transpose_ctx<<<dim3(16, 32, 8), dim3(32, 8)>>>(ctx);                    // 1: px + qx
    pack_act<<<(512 * 1024 / 8) / 256, 256>>>(nl_vw[0], qvw[0], 512, 1024);  // 2
    pack_act<<<(1024 * 512 / 8) / 256, 256>>>(nl_ow[0], qow[0], 1024, 512);  // 3
    tc_gemm<0, 128><<<dim3(32, 4), 256, SM128>>>(                            // 4: V -> qv packed
        qx, qvw[0], (float*)qv, NTOT, NTOT, 512, 16, NTOT, nullptr, nullptr);

    pack_act<<<(512 * 1024 / 8) / 256, 256>>>(nl_vw[1], qvw[1], 512, 1024);
    pack_act<<<(1024 * 512 / 8) / 256, 256>>>(nl_ow[1], qow[1], 1024, 512);
    pe_init<<<2048, 256>>>();
    pack_frame<<<dim3(24, 32, 2), dim3(32, 8)>>>(frame);                     // qfb only
    pack_wd<<<dim3(32, 8), 256>>>(up1_w, qw1, 1024);
    pack_wd<<<dim3(16, 8), 256>>>(up2_w, qw2, 512);
    pack_wconv<<<dim3(512, 4), 256>>>(tp_w);
    zero_kernel<<<(PCONV * 512 + 255) / 256, 256>>>(pconv, PCONV * 512);

    for (int l = 0; l < 2; l++) {
        if (l == 1)
            tc_gemm<0, 128><<<dim3(32, 4), 256, SM128>>>(
                qx, qvw[1], (float*)qv, NTOT, NTOT, 512, 16, NTOT, nullptr, nullptr);
        tc_gemm<1, 128><<<dim3(32, 8), 256, SM128>>>(
            qv, qow[l], py, NTOT, NTOT, 1024, 8, 1024, nl_ob[l], px);
        zero_kernel<<<8, 256>>>(pbns, 2048);
        bn_reduce<<<128, 256>>>(py);
        bn_apply<<<4096, 256>>>(py, px, (uint32_t*)qx, nl_g[l], nl_beta[l]);
    }

    // conv3d: packed A gathered from pk_x, z = 16 K-splits of 27 chunks (432 total)
    tc_gemm<5, 128><<<dim3(13, 4, 16), 256, SM128>>>(
        qx, qwc, pconv, PCONV, NTOT, 512, 27, 512, nullptr, nullptr);
    goalpre_kernel<<<4, 512>>>(tp_b);

    tc_gemm<3, 64><<<dim3(24, 4, 4), 256, SM64>>>(
        qfb, qw1, (float*)qs1, 1536, 1536, 512, 16, 6144, up1_b, nullptr);
    tc_gemm<4, 128><<<dim3(48, 4, 4), 256, SM128>>>(
        qs1, qw2, ps2, 6144, 6144, 512, 8, 512, up2_b, nullptr);

    sg_dot<<<dim3(24, 16), 256>>>();
    softmax_norm<<<24, 256>>>();
    zero_kernel<<<48, 256>>>(psga, BT * 512);
    sga_kernel<<<dim3(24, 8), 256>>>();

    head_kernel<<<4, 512>>>(pgp, (const float*)d_in[22], (const float*)d_in[23],
                            (const float*)d_in[24], (const float*)d_in[25], out);
    head_kernel<<<BT, 512>>>(psga, (const float*)d_in[26], (const float*)d_in[27],
                             (const float*)d_in[28], (const float*)d_in[29], out + 4 * OUTD);
}

// round 16
// speedup vs baseline: 1.1637x; 1.0683x over previous
#include <cuda_runtime.h>
#include <cuda_fp16.h>
#include <cstdint>
#include <math.h>

#define CIN   1024
#define FFD   512
#define OUTD  128
#define NTOT  4096
#define KCONV 27648
#define PCONV 1568
#define BT    24
#define NS    1024
#define SM64  73728
#define SM128 98304

// ---------- fp32 scratch ----------
__device__ float g_x[(size_t)NTOT * CIN];
__device__ float g_y[(size_t)NTOT * CIN];
__device__ float g_conv[(size_t)PCONV * FFD];
__device__ float g_gp[4 * FFD];
__device__ float g_s2[(size_t)(BT * 1024) * FFD];
__device__ float g_pe[(size_t)NS * FFD];
__device__ float g_attn[BT * NS];
__device__ float g_sga[BT * FFD];
__device__ float g_bns[2048];
// ---------- packed fp16 operands, GLOBALLY PRE-SWIZZLED:
// [chunk of 64 K][row][granule g stored at g^(row&7)], 8x16B per row ----------
__device__ uint4 pk_x[16 * NTOT * 8];
__device__ uint4 pk_v[8 * NTOT * 8];
__device__ uint4 pk_fb[16 * (BT * 64) * 8];
__device__ uint4 pk_s1[8 * (BT * 1024) * 8];
__device__ uint4 pk_wc[432 * FFD * 8];
__device__ uint4 pk_vw[2][16 * FFD * 8];
__device__ uint4 pk_ow[2][8 * CIN * 8];
__device__ uint4 pk_w1[4 * 16 * FFD * 8];
__device__ uint4 pk_w2[4 * 8 * FFD * 8];

// ---------- helpers ----------
__device__ __forceinline__ uint32_t smem_u32(const void* p) {
    uint32_t a;
    asm("{ .reg .u64 t; cvta.to.shared.u64 t, %1; cvt.u32.u64 %0, t; }" : "=r"(a) : "l"(p));
    return a;
}
#define LDSM4(r0, r1, r2, r3, addr) \
    asm volatile("ldmatrix.sync.aligned.m8n8.x4.shared.b16 {%0,%1,%2,%3}, [%4];" \
        : "=r"(r0), "=r"(r1), "=r"(r2), "=r"(r3) : "r"(addr))
#define MMA(c, a, b0, b1) \
    asm volatile("mma.sync.aligned.m16n8k16.row.col.f32.f16.f16.f32 " \
        "{%0,%1,%2,%3},{%4,%5,%6,%7},{%8,%9},{%0,%1,%2,%3};" \
        : "+f"((c)[0]), "+f"((c)[1]), "+f"((c)[2]), "+f"((c)[3]) \
        : "r"((a)[0]), "r"((a)[1]), "r"((a)[2]), "r"((a)[3]), "r"(b0), "r"(b1))
#define CP16(dst, src) \
    asm volatile("cp.async.cg.shared.global [%0], [%1], 16;" :: "r"(dst), "l"(src))
#define CPCOMMIT() asm volatile("cp.async.commit_group;" ::: "memory")
#define CPWAIT(n)  asm volatile("cp.async.wait_group %0;" :: "n"(n) : "memory")
#define MBAR_INIT(mb, c) \
    asm volatile("mbarrier.init.shared.b64 [%0], %1;" :: "r"(mb), "r"(c) : "memory")
#define MBAR_EXPECT(mb, bytes) \
    asm volatile("mbarrier.arrive.expect_tx.shared.b64 _, [%0], %1;" :: "r"(mb), "r"(bytes) : "memory")
#define BULK(dst, src, sz, mb) \
    asm volatile("cp.async.bulk.shared::cta.global.mbarrier::complete_tx::bytes [%0], [%1], %2, [%3];" \
        :: "r"(dst), "l"(src), "r"(sz), "r"(mb) : "memory")
#define MB_WAIT(mb, ph) do { \
    uint32_t _m = (mb), _p = (ph), _d; \
    asm volatile("{\n\t.reg .pred p;\n\t" \
      "mbarrier.try_wait.parity.acquire.cta.shared::cta.b64 p, [%1], %2;\n\t" \
      "selp.b32 %0, 1, 0, p;\n\t}" : "=r"(_d) : "r"(_m), "r"(_p) : "memory"); \
    if (!_d) { \
      asm volatile("{\n\t.reg .pred P1;\n\tWL_%=:\n\t" \
        "mbarrier.try_wait.parity.acquire.cta.shared::cta.b64 P1, [%0], %1, 0x989680;\n\t" \
        "@P1 bra.uni WD_%=;\n\tbra.uni WL_%=;\n\tWD_%=:\n\t}" :: "r"(_m), "r"(_p) : "memory"); \
    } \
} while (0)

__device__ __forceinline__ uint32_t pk2(float hi, float lo) {
    uint32_t r;
    asm("cvt.rn.f16x2.f32 %0, %1, %2;" : "=r"(r) : "f"(hi), "f"(lo));
    return r;
}
__device__ __forceinline__ uint4 pack8(float4 a, float4 b) {
    uint4 h;
    h.x = pk2(a.y, a.x); h.y = pk2(a.w, a.z);
    h.z = pk2(b.y, b.x); h.w = pk2(b.w, b.z);
    return h;
}
__device__ __forceinline__ uint32_t swz(uint32_t o) { return o ^ ((o >> 3) & 0x70u); }

// fp32 [M][K] -> packed fp16, swizzled-global
__global__ void pack_act(const float* __restrict__ src, uint4* __restrict__ dst, int M, int K) {
    int idx = blockIdx.x * 256 + threadIdx.x;
    int kg = K >> 3;
    int row = idx / kg, u = idx - row * kg;
    int chunk = u >> 3, g = u & 7;
    const float* s = src + (size_t)row * K + u * 8;
    float4 a = *(const float4*)s, b = *(const float4*)(s + 4);
    dst[((size_t)chunk * M + row) * 8 + (g ^ (row & 7))] = pack8(a, b);
}
__global__ void pack_wconv(const float* __restrict__ w) {   // grid (512, 4)
    __shared__ float st[27][260];
    int f = blockIdx.x, c0 = blockIdx.y * 256;
    const float* src = w + (size_t)f * KCONV + (size_t)c0 * 27;
    for (int i = threadIdx.x; i < 27 * 256; i += 256) {
        int c = i / 27, r = i - c * 27;
        st[r][c] = src[i];
    }
    if (blockIdx.y == 0)
        for (int i = threadIdx.x; i < PCONV; i += 256)
            g_conv[(size_t)i * 512 + f] = 0.f;
    __syncthreads();
    for (int u = threadIdx.x; u < 27 * 32; u += 256) {
        int r = u >> 5, grp = u & 31;
        const float* p = &st[r][grp * 8];
        float4 a = make_float4(p[0], p[1], p[2], p[3]);
        float4 b = make_float4(p[4], p[5], p[6], p[7]);
        int chunk = r * 16 + (c0 >> 6) + (grp >> 3);
        pk_wc[((size_t)chunk * FFD + f) * 8 + ((grp & 7) ^ (f & 7))] = pack8(a, b);
    }
}
__global__ void pack_wd(const float* __restrict__ w, uint4* __restrict__ dst, int Cdim) {
    __shared__ float st[4][32][65];
    int c0 = blockIdx.x * 32, o0 = blockIdx.y * 64;
    for (int t = threadIdx.x; t < 2048; t += 256) {
        int c = t >> 6, o = t & 63;
        float4 v = reinterpret_cast<const float4*>(w)[(size_t)(c0 + c) * 512 + o0 + o];
        st[0][c][o] = v.x; st[1][c][o] = v.y; st[2][c][o] = v.z; st[3][c][o] = v.w;
    }
    __syncthreads();
    size_t kls = (size_t)(Cdim >> 6) * 512 * 8;
    for (int t = threadIdx.x; t < 1024; t += 256) {
        int kl = t >> 8, o = (t >> 2) & 63, g = t & 3;
        float4 a, b;
        a.x = st[kl][g * 8 + 0][o]; a.y = st[kl][g * 8 + 1][o];
        a.z = st[kl][g * 8 + 2][o]; a.w = st[kl][g * 8 + 3][o];
        b.x = st[kl][g * 8 + 4][o]; b.y = st[kl][g * 8 + 5][o];
        b.z = st[kl][g * 8 + 6][o]; b.w = st[kl][g * 8 + 7][o];
        int chunk = c0 >> 6, gb = ((c0 & 63) >> 3) + g;
        dst[kl * kls + ((size_t)chunk * 512 + o0 + o) * 8 + (gb ^ (o & 7))] = pack8(a, b);
    }
}

// ===== bulk-copy 3-stage warp-MMA fp16 GEMM, tile BM x 128N, warps 2m x 4n =====
// MODE 0 packed-fp16 out | 1 xin+relu(v+bias) fp32 | 3 up1 scatter relu packed-fp16 |
// MODE 4 up2 scatter fp32 | 5 conv atomicAdd (A via cp.async gather)
template <int MODE, int BM>
__global__ void __launch_bounds__(256, 2) tc_gemm(
    const uint4* __restrict__ Apk, const uint4* __restrict__ Bpk, float* __restrict__ C,
    int Mtot, int Ma, int Nbr, int Sloc, int ldc,
    const float* __restrict__ bias, const float* __restrict__ xin)
{
    constexpr int MT = BM / 32;
    constexpr uint32_t ABYTES = BM * 128;
    constexpr uint32_t STRIDE = ABYTES + 16384;
    extern __shared__ char dsm[];
    __shared__ alignas(8) unsigned long long s_mb[3];
    const uint32_t smb = smem_u32(dsm);
    const int tid = threadIdx.x, wid = tid >> 5, lane = tid & 31;
    const int wm = wid >> 2, wn = wid & 3;
    const int row0 = blockIdx.x * BM;
    const int colW = blockIdx.y * 128;
    const int z = blockIdx.z;
    const int kchunk0 = (MODE == 5) ? z * Sloc : 0;
    if (MODE == 3 || MODE == 4) Bpk += (size_t)z * Sloc * Nbr * 8;

    if (tid < 3) MBAR_INIT(smem_u32(&s_mb[tid]), 1);
    __syncthreads();
    const uint32_t mb0 = smem_u32(&s_mb[0]);

    int nbrow = 0;
    const int g0 = (tid & 1) * 4;
    const int arow = tid >> 1;
    if (MODE == 5) {
        int p = row0 + arow;
        if (p >= Mtot) p = Mtot - 1;
        int b = p / 392, q = p % 392;
        int t = q / 196, rem = q % 196, h = rem / 14, w = rem % 14;
        nbrow = (b * 4 + t) * 256 + h * 16 + w;
    }

    auto issue = [&](int s, int buf) {
        int sg = kchunk0 + s;
        uint32_t sb = smb + (uint32_t)buf * STRIDE;
        uint32_t mb = mb0 + (uint32_t)buf * 8;
        if (MODE == 5) {
            // A gathered per-thread; translate global-row swizzle -> smem-row swizzle
            int rk = sg >> 4, cc = sg & 15;
            int dt = rk / 9, dh = (rk / 3) % 3, dw = rk - (rk / 3) * 3;
            int grow = nbrow + dt * 256 + dh * 16 + dw;
            const uint4* abase = Apk + ((size_t)cc * Ma + grow) * 8;
            uint32_t drow = sb + (uint32_t)(arow * 128);
            int gsw = grow & 7, asw = arow & 7;
#pragma unroll
            for (int g = 0; g < 4; g++) {
                int lg = g0 + g;
                CP16(drow + (uint32_t)((lg ^ asw) * 16), abase + (lg ^ gsw));
            }
            CPCOMMIT();
            if (tid == 0) {
                MBAR_EXPECT(mb, 16384u);
                BULK(sb + ABYTES, (const char*)(Bpk + ((size_t)sg * Nbr + colW) * 8), 16384u, mb);
            }
        } else {
            if (tid == 0) {
                MBAR_EXPECT(mb, ABYTES + 16384u);
                BULK(sb, (const char*)(Apk + ((size_t)sg * Ma + row0) * 8), ABYTES, mb);
                BULK(sb + ABYTES, (const char*)(Bpk + ((size_t)sg * Nbr + colW) * 8), 16384u, mb);
            }
        }
    };

    float acc[MT][4][4];
#pragma unroll
    for (int i = 0; i < MT; i++)
#pragma unroll
        for (int j = 0; j < 4; j++)
#pragma unroll
            for (int e = 0; e < 4; e++) acc[i][j][e] = 0.f;

    issue(0, 0);
    issue(1, 1);

    const int q = lane >> 3, rl = lane & 7;
    for (int s = 0; s < Sloc; s++) {
        const int buf = s % 3;
        if (MODE == 5) {
            if (s + 1 < Sloc) { CPWAIT(1); } else { CPWAIT(0); }
        }
        MB_WAIT(mb0 + (uint32_t)buf * 8, (s / 3) & 1);
        __syncthreads();
        if (s + 2 < Sloc) issue(s + 2, (s + 2) % 3);
        const uint32_t aB = smb + (uint32_t)buf * STRIDE;
        const uint32_t bB = aB + ABYTES;
#pragma unroll
        for (int ks = 0; ks < 4; ks++) {
            uint32_t ah[MT][4];
            uint32_t ao = swz((uint32_t)((wm * (BM / 2) + (q & 1) * 8 + rl) * 128 + ks * 32 + (q >> 1) * 16));
#pragma unroll
            for (int mt = 0; mt < MT; mt++)
                LDSM4(ah[mt][0], ah[mt][1], ah[mt][2], ah[mt][3], aB + ao + mt * 2048);
            uint32_t bo = swz((uint32_t)((wn * 32 + (q >> 1) * 8 + rl) * 128 + ks * 32 + (q & 1) * 16));
#pragma unroll
            for (int pt = 0; pt < 2; pt++) {
                uint32_t bh[4];
                LDSM4(bh[0], bh[1], bh[2], bh[3], bB + bo + pt * 2048);
#pragma unroll
                for (int mt = 0; mt < MT; mt++) {
                    MMA(acc[mt][2 * pt],     ah[mt], bh[0], bh[1]);
                    MMA(acc[mt][2 * pt + 1], ah[mt], bh[2], bh[3]);
                }
            }
        }
        __syncthreads();
    }

    // epilogue
#pragma unroll
    for (int mt = 0; mt < MT; mt++) {
#pragma unroll
        for (int nt = 0; nt < 4; nt++) {
            int f = colW + wn * 32 + nt * 8 + 2 * (lane & 3);
            float b0 = 0.f, b1 = 0.f;
            if (MODE == 1 || MODE == 3 || MODE == 4) { b0 = bias[f]; b1 = bias[f + 1]; }
#pragma unroll
            for (int hh = 0; hh < 2; hh++) {
                int pos = row0 + wm * (BM / 2) + mt * 16 + (lane >> 2) + hh * 8;
                if (pos >= Mtot) continue;
                float v0 = acc[mt][nt][hh * 2], v1 = acc[mt][nt][hh * 2 + 1];
                if (MODE == 0) {
                    int w = (f & 63) >> 1, g = (w >> 2) ^ (pos & 7);
                    reinterpret_cast<uint32_t*>(C)[
                        ((size_t)(f >> 6) * ldc + pos) * 32 + g * 4 + (w & 3)] = pk2(v1, v0);
                } else if (MODE == 1) {
                    float2 xv = *reinterpret_cast<const float2*>(&xin[(size_t)pos * ldc + f]);
                    *reinterpret_cast<float2*>(&C[(size_t)pos * ldc + f]) =
                        make_float2(xv.x + fmaxf(v0 + b0, 0.f), xv.y + fmaxf(v1 + b1, 0.f));
                } else if (MODE == 5) {
                    atomicAdd(&C[(size_t)pos * ldc + f], v0);
                    atomicAdd(&C[(size_t)pos * ldc + f + 1], v1);
                } else if (MODE == 3) {
                    int bt = pos >> 6, hw = pos & 63, h = hw >> 3, w2 = hw & 7;
                    int orow = bt * 256 + (h * 2 + (z >> 1)) * 16 + (w2 * 2 + (z & 1));
                    float s0 = fmaxf(v0 + b0, 0.f), s1v = fmaxf(v1 + b1, 0.f);
                    int w = (f & 63) >> 1, g = (w >> 2) ^ (orow & 7);
                    reinterpret_cast<uint32_t*>(C)[
                        ((size_t)(f >> 6) * ldc + orow) * 32 + g * 4 + (w & 3)] = pk2(s1v, s0);
                } else {
                    int bt = pos >> 8, hw = pos & 255, h = hw >> 4, w2 = hw & 15;
                    int orow = bt * 1024 + (h * 2 + (z >> 1)) * 32 + (w2 * 2 + (z & 1));
                    *reinterpret_cast<float2*>(&C[(size_t)orow * ldc + f]) =
                        make_float2(v0 + b0, v1 + b1);
                }
            }
        }
    }
}

// ========== misc ==========
__global__ void transpose_ctx(const float* __restrict__ ctx) {
    __shared__ float t[32][33];
    int bt = blockIdx.x, c0 = blockIdx.y * 32, hw0 = blockIdx.z * 32;
    int tx = threadIdx.x, ty = threadIdx.y;
    for (int i = ty; i < 32; i += 8)
        t[i][tx] = ctx[((size_t)bt * 1024 + c0 + i) * 256 + hw0 + tx];
    __syncthreads();
    for (int i = ty; i < 32; i += 8)
        g_x[((size_t)bt * 256 + hw0 + i) * 1024 + c0 + tx] = t[tx][i];
    int tid = ty * 32 + tx;
    if (tid < 128) {
        int ii = tid >> 2, j = tid & 3;
        int n = bt * 256 + hw0 + ii;
        float4 a, b;
        a.x = t[j * 8 + 0][ii]; a.y = t[j * 8 + 1][ii]; a.z = t[j * 8 + 2][ii]; a.w = t[j * 8 + 3][ii];
        b.x = t[j * 8 + 4][ii]; b.y = t[j * 8 + 5][ii]; b.z = t[j * 8 + 6][ii]; b.w = t[j * 8 + 7][ii];
        int chunk = c0 >> 6, gb = ((c0 & 63) >> 3) + j;
        pk_x[((size_t)chunk * NTOT + n) * 8 + (gb ^ (n & 7))] = pack8(a, b);
    }
    if (blockIdx.x == 0 && blockIdx.y == 0 && blockIdx.z == 0) {
        for (int i = tid; i < 2048; i += 256) g_bns[i] = 0.f;
    }
}
__global__ void pack_frame(const float* __restrict__ fr) {
    __shared__ float t[32][33];
    int bt = blockIdx.x, c0 = blockIdx.y * 32, hw0 = blockIdx.z * 32;
    int tx = threadIdx.x, ty = threadIdx.y;
    for (int i = ty; i < 32; i += 8)
        t[i][tx] = fr[((size_t)bt * 1024 + c0 + i) * 64 + hw0 + tx];
    __syncthreads();
    int tid = ty * 32 + tx;
    if (tid < 128) {
        int ii = tid >> 2, j = tid & 3;
        int n = bt * 64 + hw0 + ii;
        float4 a, b;
        a.x = t[j * 8 + 0][ii]; a.y = t[j * 8 + 1][ii]; a.z = t[j * 8 + 2][ii]; a.w = t[j * 8 + 3][ii];
        b.x = t[j * 8 + 4][ii]; b.y = t[j * 8 + 5][ii]; b.z = t[j * 8 + 6][ii]; b.w = t[j * 8 + 7][ii];
        int chunk = c0 >> 6, gb = ((c0 & 63) >> 3) + j;
        pk_fb[((size_t)chunk * (BT * 64) + n) * 8 + (gb ^ (n & 7))] = pack8(a, b);
    }
}
__global__ void zero_kernel(float* p, int n) {
    int i = blockIdx.x * blockDim.x + threadIdx.x;
    if (i < n) p[i] = 0.f;
}
__global__ void bn_reduce2(const float* __restrict__ y, float* __restrict__ bns) {
    int c4 = threadIdx.x;
    const float4* y4 = reinterpret_cast<const float4*>(y);
    float4 s = make_float4(0, 0, 0, 0), q = make_float4(0, 0, 0, 0);
    int n0 = blockIdx.x * 32;
    for (int n = n0; n < n0 + 32; n++) {
        float4 v = y4[(size_t)n * 256 + c4];
        s.x += v.x; s.y += v.y; s.z += v.z; s.w += v.w;
        q.x += v.x * v.x; q.y += v.y * v.y; q.z += v.z * v.z; q.w += v.w * v.w;
    }
    atomicAdd(&bns[c4 * 4 + 0], s.x); atomicAdd(&bns[c4 * 4 + 1], s.y);
    atomicAdd(&bns[c4 * 4 + 2], s.z); atomicAdd(&bns[c4 * 4 + 3], s.w);
    atomicAdd(&bns[1024 + c4 * 4 + 0], q.x); atomicAdd(&bns[1024 + c4 * 4 + 1], q.y);
    atomicAdd(&bns[1024 + c4 * 4 + 2], q.z); atomicAdd(&bns[1024 + c4 * 4 + 3], q.w);
}
__global__ void bn_apply(const float* __restrict__ y, float* __restrict__ xo,
                         uint32_t* __restrict__ qdst, const float* __restrict__ bns,
                         const float* __restrict__ gm, const float* __restrict__ bt) {
    int idx = blockIdx.x * 256 + threadIdx.x;
    int n = idx >> 8, c4 = idx & 255;
    float4 v = reinterpret_cast<const float4*>(y)[idx];
    float4 s = reinterpret_cast<const float4*>(bns)[c4];
    float4 q = reinterpret_cast<const float4*>(bns + 1024)[c4];
    float4 g = reinterpret_cast<const float4*>(gm)[c4];
    float4 b = reinterpret_cast<const float4*>(bt)[c4];
    const float in = 1.f / NTOT;
    float mx = s.x * in, my = s.y * in, mz = s.z * in, mw = s.w * in;
    float4 r;
    r.x = (v.x - mx) * rsqrtf(q.x * in - mx * mx + 1e-5f) * g.x + b.x;
    r.y = (v.y - my) * rsqrtf(q.y * in - my * my + 1e-5f) * g.y + b.y;
    r.z = (v.z - mz) * rsqrtf(q.z * in - mz * mz + 1e-5f) * g.z + b.z;
    r.w = (v.w - mw) * rsqrtf(q.w * in - mw * mw + 1e-5f) * g.w + b.w;
    reinterpret_cast<float4*>(xo)[idx] = r;
    int ga = (c4 >> 1) & 7;
    size_t base = (((size_t)(c4 >> 4) * NTOT + n) * 8 + (ga ^ (n & 7))) * 4 + (c4 & 1) * 2;
    qdst[base] = pk2(r.y, r.x);
    qdst[base + 1] = pk2(r.w, r.z);
}
__global__ void goalpre_kernel(const float* __restrict__ tb) {
    int b = blockIdx.x, f = threadIdx.x;
    float bias = tb[f], s = 0.f;
    for (int p = b * 392; p < (b + 1) * 392; p++)
        s += fmaxf(g_conv[(size_t)p * 512 + f] + bias, 0.f);
    g_gp[b * 512 + f] = s * (1.f / 392.f);
}
__global__ void pe_init() {
    int idx = blockIdx.x * 256 + threadIdx.x;
    int n = idx >> 9, c = idx & 511;
    float ang = (float)n * expf(-0.01798894603890390f * (float)(c & ~1));
    g_pe[idx] = (c & 1) ? cosf(ang) : sinf(ang);
}
__global__ void sg_dot() {
    int bt = blockIdx.x, n0 = blockIdx.y * 64;
    int w = threadIdx.x >> 5, lane = threadIdx.x & 31;
    int b = bt / 6;
    const float4* g4 = reinterpret_cast<const float4*>(&g_gp[b * 512]);
#pragma unroll
    for (int j = 0; j < 8; j++) {
        int n = n0 + w * 8 + j;
        const float4* r4 = reinterpret_cast<const float4*>(&g_s2[((size_t)bt * 1024 + n) * 512]);
        float acc = 0.f;
#pragma unroll
        for (int i = 0; i < 4; i++) {
            float4 v = r4[lane + 32 * i], gg = g4[lane + 32 * i];
            acc += v.x * gg.x + v.y * gg.y + v.z * gg.z + v.w * gg.w;
        }
        for (int o = 16; o > 0; o >>= 1) acc += __shfl_down_sync(0xffffffffu, acc, o);
        if (!lane) g_attn[bt * 1024 + n] = acc;
    }
}
__global__ void softmax_norm() {
    int bt = blockIdx.x, tid = threadIdx.x;
    __shared__ float red[256];
    float v[4];
#pragma unroll
    for (int i = 0; i < 4; i++) v[i] = g_attn[bt * 1024 + tid + i * 256];
    float m = fmaxf(fmaxf(v[0], v[1]), fmaxf(v[2], v[3]));
    red[tid] = m; __syncthreads();
    for (int o = 128; o > 0; o >>= 1) { if (tid < o) red[tid] = fmaxf(red[tid], red[tid + o]); __syncthreads(); }
    m = red[0]; __syncthreads();
    float s = 0.f;
#pragma unroll
    for (int i = 0; i < 4; i++) { v[i] = expf(v[i] - m); s += v[i]; }
    red[tid] = s; __syncthreads();
    for (int o = 128; o > 0; o >>= 1) { if (tid < o) red[tid] += red[tid + o]; __syncthreads(); }
    float inv = 1.f / red[0];
#pragma unroll
    for (int i = 0; i < 4; i++) g_attn[bt * 1024 + tid + i * 256] = v[i] * inv;
}
__global__ void sga_kernel() {
    int bt = blockIdx.x, n0 = blockIdx.y * 128, c2 = threadIdx.x;
    float a0 = 0.f, a1 = 0.f;
    for (int n = n0; n < n0 + 128; n++) {
        float at = g_attn[bt * 1024 + n];
        float2 s = *reinterpret_cast<const float2*>(&g_s2[((size_t)bt * 1024 + n) * 512 + c2 * 2]);
        float2 p = *reinterpret_cast<const float2*>(&g_pe[(size_t)n * 512 + c2 * 2]);
        a0 += at * (s.x + p.x); a1 += at * (s.y + p.y);
    }
    atomicAdd(&g_sga[bt * 512 + c2 * 2], a0);
    atomicAdd(&g_sga[bt * 512 + c2 * 2 + 1], a1);
}
__global__ void head_kernel(const float* __restrict__ in,
                            const float* __restrict__ W1, const float* __restrict__ b1,
                            const float* __restrict__ W2, const float* __restrict__ b2,
                            float* __restrict__ out) {
    int r = blockIdx.x, j = threadIdx.x;
    __shared__ float xin[512], t[512];
    xin[j] = in[r * 512 + j];
    __syncthreads();
    float acc = b1[j];
    const float* w = W1 + (size_t)j * 512;
    for (int k = 0; k < 512; k++) acc += xin[k] * w[k];
    t[j] = fmaxf(acc, 0.f);
    __syncthreads();
    if (j < OUTD) {
        float a2 = b2[j];
        const float* w2 = W2 + (size_t)j * 512;
        for (int k = 0; k < 512; k++) a2 += t[k] * w2[k];
        out[r * OUTD + j] = a2;
    }
}

// ---------- launch ----------
extern "C" void kernel_launch(void* const* d_in, const int* in_sizes, int n_in,
                              void* d_out, int out_size) {
    const float* ctx   = (const float*)d_in[0];
    const float* frame = (const float*)d_in[1];
    const float* nl_vw[2]   = { (const float*)d_in[4],  (const float*)d_in[11] };
    const float* nl_ow[2]   = { (const float*)d_in[5],  (const float*)d_in[12] };
    const float* nl_ob[2]   = { (const float*)d_in[6],  (const float*)d_in[13] };
    const float* nl_g[2]    = { (const float*)d_in[7],  (const float*)d_in[14] };
    const float* nl_beta[2] = { (const float*)d_in[8],  (const float*)d_in[15] };
    const float* tp_w  = (const float*)d_in[16];
    const float* tp_b  = (const float*)d_in[17];
    const float* up1_w = (const float*)d_in[18];
    const float* up1_b = (const float*)d_in[19];
    const float* up2_w = (const float*)d_in[20];
    const float* up2_b = (const float*)d_in[21];
    float* out = (float*)d_out;

    float *px, *py, *pconv, *ps2, *pgp, *psga, *pbns;
    cudaGetSymbolAddress((void**)&px, g_x);
    cudaGetSymbolAddress((void**)&py, g_y);
    cudaGetSymbolAddress((void**)&pconv, g_conv);
    cudaGetSymbolAddress((void**)&ps2, g_s2);
    cudaGetSymbolAddress((void**)&pgp, g_gp);
    cudaGetSymbolAddress((void**)&psga, g_sga);
    cudaGetSymbolAddress((void**)&pbns, g_bns);
    uint4 *qx, *qv, *qfb, *qs1, *qwc, *qvw0, *qvw1, *qow0, *qow1, *qw1, *qw2;
    cudaGetSymbolAddress((void**)&qx, pk_x);
    cudaGetSymbolAddress((void**)&qv, pk_v);
    cudaGetSymbolAddress((void**)&qfb, pk_fb);
    cudaGetSymbolAddress((void**)&qs1, pk_s1);
    cudaGetSymbolAddress((void**)&qwc, pk_wc);
    cudaGetSymbolAddress((void**)&qvw0, pk_vw); qvw1 = qvw0 + 16 * FFD * 8;
    cudaGetSymbolAddress((void**)&qow0, pk_ow); qow1 = qow0 + 8 * CIN * 8;
    cudaGetSymbolAddress((void**)&qw1, pk_w1);
    cudaGetSymbolAddress((void**)&qw2, pk_w2);
    uint4* qvw[2] = { qvw0, qvw1 };
    uint4* qow[2] = { qow0, qow1 };

    cudaFuncSetAttribute((const void*)tc_gemm<0, 128>, cudaFuncAttributeMaxDynamicSharedMemorySize, SM128);
    cudaFuncSetAttribute((const void*)tc_gemm<1, 128>, cudaFuncAttributeMaxDynamicSharedMemorySize, SM128);
    cudaFuncSetAttribute((const void*)tc_gemm<3, 64>,  cudaFuncAttributeMaxDynamicSharedMemorySize, SM64);
    cudaFuncSetAttribute((const void*)tc_gemm<4, 128>, cudaFuncAttributeMaxDynamicSharedMemorySize, SM128);
    cudaFuncSetAttribute((const void*)tc_gemm<5, 128>, cudaFuncAttributeMaxDynamicSharedMemorySize, SM128);

    transpose_ctx<<<dim3(16, 32, 8), dim3(32, 8)>>>(ctx);                    // 1 (+ zero g_bns)
    pack_act<<<(512 * 1024 / 8) / 256, 256>>>(nl_vw[0], qvw[0], 512, 1024);  // 2
    pack_act<<<(1024 * 512 / 8) / 256, 256>>>(nl_ow[0], qow[0], 1024, 512);  // 3
    tc_gemm<0, 128><<<dim3(32, 4), 256, SM128>>>(                            // 4 (profiled)
        qx, qvw[0], (float*)qv, NTOT, NTOT, 512, 16, NTOT, nullptr, nullptr);

    pack_act<<<(512 * 1024 / 8) / 256, 256>>>(nl_vw[1], qvw[1], 512, 1024);
    pack_act<<<(1024 * 512 / 8) / 256, 256>>>(nl_ow[1], qow[1], 1024, 512);
    pe_init<<<2048, 256>>>();
    pack_frame<<<dim3(24, 32, 2), dim3(32, 8)>>>(frame);
    pack_wd<<<dim3(32, 8), 256>>>(up1_w, qw1, 1024);
    pack_wd<<<dim3(16, 8), 256>>>(up2_w, qw2, 512);
    pack_wconv<<<dim3(512, 4), 256>>>(tp_w);    // + zero g_conv

    for (int l = 0; l < 2; l++) {
        if (l == 1)
            tc_gemm<0, 128><<<dim3(32, 4), 256, SM128>>>(
                qx, qvw[1], (float*)qv, NTOT, NTOT, 512, 16, NTOT, nullptr, nullptr);
        tc_gemm<1, 128><<<dim3(32, 8), 256, SM128>>>(
            qv, qow[l], py, NTOT, NTOT, 1024, 8, 1024, nl_ob[l], px);
        bn_reduce2<<<128, 256>>>(py, pbns);
        bn_apply<<<4096, 256>>>(py, px, (uint32_t*)qx, pbns, nl_g[l], nl_beta[l]);
        if (l == 0) zero_kernel<<<8, 256>>>(pbns, 2048);
    }

    // conv3d: packed A gathered from pk_x, z = 16 K-splits of 27 chunks
    tc_gemm<5, 128><<<dim3(13, 4, 16), 256, SM128>>>(
        qx, qwc, pconv, PCONV, NTOT, 512, 27, 512, nullptr, nullptr);
    goalpre_kernel<<<4, 512>>>(tp_b);

    tc_gemm<3, 64><<<dim3(24, 4, 4), 256, SM64>>>(
        qfb, qw1, (float*)qs1, 1536, 1536, 512, 16, 6144, up1_b, nullptr);
    tc_gemm<4, 128><<<dim3(48, 4, 4), 256, SM128>>>(
        qs1, qw2, ps2, 6144, 6144, 512, 8, 512, up2_b, nullptr);

    sg_dot<<<dim3(24, 16), 256>>>();
    softmax_norm<<<24, 256>>>();
    zero_kernel<<<48, 256>>>(psga, BT * 512);
    sga_kernel<<<dim3(24, 8), 256>>>();

    head_kernel<<<4, 512>>>(pgp, (const float*)d_in[22], (const float*)d_in[23],
                            (const float*)d_in[24], (const float*)d_in[25], out);
    head_kernel<<<BT, 512>>>(psga, (const float*)d_in[26], (const float*)d_in[27],
                             (const float*)d_in[28], (const float*)d_in[29], out + 4 * OUTD);
}